// round 5
// baseline (speedup 1.0000x reference)
#include <cuda_runtime.h>
#include <math.h>

#define BATCH 4
#define HI 128
#define WI 128
#define HO 64
#define WO 64
#define DIM 128
#define NPIX_IN  (HI*WI)        // 16384
#define NPIX_OUT (HO*WO)        // 4096
#define NROWS_IN  (BATCH*NPIX_IN)   // 65536
#define NROWS_OUT (BATCH*NPIX_OUT)  // 16384

// ---------------- scratch (device globals) ----------------------------------
__device__ float g_cwT[9*DIM*DIM];                       // conv weights [tap][i][o]
__device__ float g_k   [(size_t)NROWS_IN*DIM];
__device__ float g_v   [(size_t)NROWS_IN*DIM];
__device__ float g_xln [(size_t)NROWS_IN*DIM];           // LN-ed activations
__device__ float g_xout[(size_t)NROWS_OUT*DIM];
__device__ float g_q   [(size_t)NROWS_OUT*DIM];
__device__ float g_h   [(size_t)NROWS_OUT*2*DIM];
__device__ float g_colsum[BATCH*NPIX_OUT];

// ---------------- helpers ----------------------------------------------------
static __device__ __forceinline__ float wredsum(float v){
#pragma unroll
    for (int o = 16; o > 0; o >>= 1) v += __shfl_xor_sync(0xffffffffu, v, o);
    return v;
}
static __device__ __forceinline__ float redsum16(float v){
#pragma unroll
    for (int o = 8; o > 0; o >>= 1) v += __shfl_xor_sync(0xffffffffu, v, o);
    return v;
}
static __device__ __forceinline__ float geluf(float x){
    return 0.5f * x * (1.0f + erff(x * 0.70710678118654752440f));
}

// ---------------- conv weight transpose: [o][i][kh][kw] -> [tap][i][o] -------
__global__ void transpose_cw_kernel(const float* __restrict__ cw){
    int idx = blockIdx.x * blockDim.x + threadIdx.x;
    if (idx >= 9*DIM*DIM) return;
    int o   = idx / (DIM*9);
    int rem = idx - o*(DIM*9);
    int i   = rem / 9;
    int tap = rem - i*9;
    g_cwT[(size_t)tap*DIM*DIM + i*DIM + o] = cw[idx];
}

// ---------------- standalone LayerNorm (warp per row) ------------------------
__global__ void __launch_bounds__(256) ln_kernel(
    const float* __restrict__ in, float* __restrict__ out,
    const float* __restrict__ g, const float* __restrict__ b)
{
    const int lane = threadIdx.x & 31, warp = threadIdx.x >> 5;
    const int row = blockIdx.x*8 + warp;
    float4 v = reinterpret_cast<const float4*>(in + (size_t)row*DIM)[lane];
    float mu = wredsum(v.x+v.y+v.z+v.w) * (1.0f/DIM);
    float dx=v.x-mu, dy=v.y-mu, dz=v.z-mu, dw=v.w-mu;
    float var = wredsum(dx*dx+dy*dy+dz*dz+dw*dw) * (1.0f/DIM);
    float rs = rsqrtf(var + 1e-5f);
    float4 gg = reinterpret_cast<const float4*>(g)[lane];
    float4 bb = reinterpret_cast<const float4*>(b)[lane];
    float4 o;
    o.x = dx*rs*gg.x + bb.x; o.y = dy*rs*gg.y + bb.y;
    o.z = dz*rs*gg.z + bb.z; o.w = dw*rs*gg.w + bb.w;
    reinterpret_cast<float4*>(out + (size_t)row*DIM)[lane] = o;
}

// ---------------- double-buffered register-tiled SGEMM -----------------------
// C[M,*] = A[M,K] @ B[K,*]; 256 threads; block tile BM x 128; micro TM x 8;
// BK = 16, ping-pong smem, register-staged global loads.
#define EPI_STORE 0
#define EPI_GELU  1
#define EPI_LNRES 2

template<int BM, int TM>
__global__ void __launch_bounds__(256) gemm_kernel(
    const float* __restrict__ A, int K,
    const float* __restrict__ B, int ldb,
    const float* __restrict__ bias,
    const float* __restrict__ lng, const float* __restrict__ lnb,
    float* __restrict__ C, int ldc,
    float* __restrict__ res, float* __restrict__ fin, float* __restrict__ xln,
    int epi, int writeFinal)
{
    constexpr int NA = BM/64;          // float4 A-loads per thread per chunk
    __shared__ __align__(16) float As[2][16][BM+4];
    __shared__ __align__(16) float Bs[2][16][128];
    const int tid = threadIdx.x;
    const int tx = tid & 15, ty = tid >> 4;
    const int mBase = blockIdx.x * BM;
    const int col0  = blockIdx.y * 128;

    float acc[TM][8];
#pragma unroll
    for (int r = 0; r < TM; r++)
#pragma unroll
        for (int c = 0; c < 8; c++) acc[r][c] = 0.f;

    const int nCh = K >> 4;
    float4 rA[NA], rB[2];

    // prologue: load chunk 0
#pragma unroll
    for (int i = 0; i < NA; i++){
        int idx = tid + i*256;
        int m = idx & (BM-1), q = idx / BM;
        rA[i] = *reinterpret_cast<const float4*>(A + (size_t)(mBase+m)*K + q*4);
    }
#pragma unroll
    for (int i = 0; i < 2; i++){
        int idx = tid + i*256;
        int c4 = idx & 31, kk = idx >> 5;
        rB[i] = *reinterpret_cast<const float4*>(B + (size_t)kk*ldb + col0 + c4*4);
    }
#pragma unroll
    for (int i = 0; i < NA; i++){
        int idx = tid + i*256;
        int m = idx & (BM-1), q = idx / BM;
        As[0][q*4+0][m] = rA[i].x; As[0][q*4+1][m] = rA[i].y;
        As[0][q*4+2][m] = rA[i].z; As[0][q*4+3][m] = rA[i].w;
    }
#pragma unroll
    for (int i = 0; i < 2; i++){
        int idx = tid + i*256;
        int c4 = idx & 31, kk = idx >> 5;
        *reinterpret_cast<float4*>(&Bs[0][kk][c4*4]) = rB[i];
    }
    __syncthreads();

    for (int ch = 0; ch < nCh; ch++){
        const int cur = ch & 1;
        const bool more = (ch + 1 < nCh);
        if (more){
            const int k0 = (ch+1) << 4;
#pragma unroll
            for (int i = 0; i < NA; i++){
                int idx = tid + i*256;
                int m = idx & (BM-1), q = idx / BM;
                rA[i] = *reinterpret_cast<const float4*>(A + (size_t)(mBase+m)*K + k0 + q*4);
            }
#pragma unroll
            for (int i = 0; i < 2; i++){
                int idx = tid + i*256;
                int c4 = idx & 31, kk = idx >> 5;
                rB[i] = *reinterpret_cast<const float4*>(B + (size_t)(k0+kk)*ldb + col0 + c4*4);
            }
        }
#pragma unroll
        for (int k = 0; k < 16; k++){
            float av[TM], bv[8];
#pragma unroll
            for (int i = 0; i < TM/4; i++){
                float4 t = *reinterpret_cast<const float4*>(&As[cur][k][ty*TM + i*4]);
                av[i*4+0]=t.x; av[i*4+1]=t.y; av[i*4+2]=t.z; av[i*4+3]=t.w;
            }
            float4 b0 = *reinterpret_cast<const float4*>(&Bs[cur][k][tx*8]);
            float4 b1 = *reinterpret_cast<const float4*>(&Bs[cur][k][tx*8+4]);
            bv[0]=b0.x; bv[1]=b0.y; bv[2]=b0.z; bv[3]=b0.w;
            bv[4]=b1.x; bv[5]=b1.y; bv[6]=b1.z; bv[7]=b1.w;
#pragma unroll
            for (int r = 0; r < TM; r++)
#pragma unroll
                for (int c = 0; c < 8; c++)
                    acc[r][c] += av[r]*bv[c];
        }
        if (more){
            const int nb = (ch+1) & 1;
#pragma unroll
            for (int i = 0; i < NA; i++){
                int idx = tid + i*256;
                int m = idx & (BM-1), q = idx / BM;
                As[nb][q*4+0][m] = rA[i].x; As[nb][q*4+1][m] = rA[i].y;
                As[nb][q*4+2][m] = rA[i].z; As[nb][q*4+3][m] = rA[i].w;
            }
#pragma unroll
            for (int i = 0; i < 2; i++){
                int idx = tid + i*256;
                int c4 = idx & 31, kk = idx >> 5;
                *reinterpret_cast<float4*>(&Bs[nb][kk][c4*4]) = rB[i];
            }
        }
        __syncthreads();
    }

    const int row0 = mBase + ty*TM;
    const int c0   = col0 + tx*8;

    if (epi == EPI_STORE){
#pragma unroll
        for (int r = 0; r < TM; r++){
            float4* cp = reinterpret_cast<float4*>(C + (size_t)(row0+r)*ldc + c0);
            cp[0] = make_float4(acc[r][0],acc[r][1],acc[r][2],acc[r][3]);
            cp[1] = make_float4(acc[r][4],acc[r][5],acc[r][6],acc[r][7]);
        }
    } else if (epi == EPI_GELU){
        float bb[8];
#pragma unroll
        for (int c = 0; c < 8; c++) bb[c] = bias[c0+c];
#pragma unroll
        for (int r = 0; r < TM; r++){
            float v[8];
#pragma unroll
            for (int c = 0; c < 8; c++) v[c] = geluf(acc[r][c] + bb[c]);
            float4* cp = reinterpret_cast<float4*>(C + (size_t)(row0+r)*ldc + c0);
            cp[0] = make_float4(v[0],v[1],v[2],v[3]);
            cp[1] = make_float4(v[4],v[5],v[6],v[7]);
        }
    } else { // EPI_LNRES: x_out += LN(acc + bias); also write xln = LN(x_out)
        float bb[8], gg[8], be[8];
#pragma unroll
        for (int c = 0; c < 8; c++){
            bb[c] = bias[c0+c]; gg[c] = lng[c0+c]; be[c] = lnb[c0+c];
        }
#pragma unroll
        for (int r = 0; r < TM; r++){
            float v[8]; float s = 0.f;
#pragma unroll
            for (int c = 0; c < 8; c++){ v[c] = acc[r][c] + bb[c]; s += v[c]; }
            float mu = redsum16(s) * (1.0f/128.0f);
            float s2 = 0.f;
#pragma unroll
            for (int c = 0; c < 8; c++){ v[c] -= mu; s2 += v[c]*v[c]; }
            float rs = rsqrtf(redsum16(s2)*(1.0f/128.0f) + 1e-5f);
            float* rp = res + (size_t)(row0+r)*DIM + c0;
            float o[8];
#pragma unroll
            for (int c = 0; c < 8; c++) o[c] = rp[c] + v[c]*rs*gg[c] + be[c];
            reinterpret_cast<float4*>(rp)[0] = make_float4(o[0],o[1],o[2],o[3]);
            reinterpret_cast<float4*>(rp)[1] = make_float4(o[4],o[5],o[6],o[7]);
            if (writeFinal){
                float* fp = fin + (size_t)(row0+r)*DIM + c0;
                reinterpret_cast<float4*>(fp)[0] = make_float4(o[0],o[1],o[2],o[3]);
                reinterpret_cast<float4*>(fp)[1] = make_float4(o[4],o[5],o[6],o[7]);
            }
            // second LN for next iteration's q-projection input
            float t = 0.f;
#pragma unroll
            for (int c = 0; c < 8; c++) t += o[c];
            float mu2 = redsum16(t) * (1.0f/128.0f);
            float t2 = 0.f;
#pragma unroll
            for (int c = 0; c < 8; c++){ o[c] -= mu2; t2 += o[c]*o[c]; }
            float rs2 = rsqrtf(redsum16(t2)*(1.0f/128.0f) + 1e-5f);
            float* xp = xln + (size_t)(row0+r)*DIM + c0;
            reinterpret_cast<float4*>(xp)[0] = make_float4(
                o[0]*rs2*gg[0]+be[0], o[1]*rs2*gg[1]+be[1],
                o[2]*rs2*gg[2]+be[2], o[3]*rs2*gg[3]+be[3]);
            reinterpret_cast<float4*>(xp)[1] = make_float4(
                o[4]*rs2*gg[4]+be[4], o[5]*rs2*gg[5]+be[5],
                o[6]*rs2*gg[6]+be[6], o[7]*rs2*gg[7]+be[7]);
        }
    }
}

// ---------------- conv: tap-looped double-buffered GEMM + double-LN ----------
// BM=64 pixels x 128 out-channels; 256 threads; 4x8 micro; K=1152 (72 chunks).
__global__ void __launch_bounds__(256) conv_kernel(
    const float* __restrict__ X,
    const float* __restrict__ lng, const float* __restrict__ lnb)
{
    __shared__ __align__(16) float As[2][16][68];
    __shared__ __align__(16) float Bs[2][16][128];
    const int tid = threadIdx.x;
    const int tx = tid & 15, ty = tid >> 4;
    const int base = blockIdx.x * 64;       // out-pixel base (same batch)
    const int b = base >> 12;

    float acc[4][8];
#pragma unroll
    for (int r = 0; r < 4; r++)
#pragma unroll
        for (int c = 0; c < 8; c++) acc[r][c] = 0.f;

    const int m  = tid & 63;                 // pixel this thread gathers
    const int qk = tid >> 6;                 // k-quad 0..3
    const int hw = (base + m) & 4095;
    const int h = hw >> 6, w = hw & 63;

    float4 rA, rB[2];
    // gather for chunk ch: tap = ch>>3, k0 = (ch&7)*16
    auto_loop_start:;
    {
        const int tap = 0, k0 = 0;
        const int kh = tap/3 - 1, kw = tap%3 - 1;
        const int hi = 2*h + kh, wi = 2*w + kw;
        rA = make_float4(0.f,0.f,0.f,0.f);
        if ((unsigned)hi < HI && (unsigned)wi < WI)
            rA = *reinterpret_cast<const float4*>(
                  X + ((size_t)b*NPIX_IN + hi*WI + wi)*DIM + k0 + qk*4);
#pragma unroll
        for (int i = 0; i < 2; i++){
            int idx = tid + i*256;
            int c4 = idx & 31, kk = idx >> 5;
            rB[i] = *reinterpret_cast<const float4*>(
                     g_cwT + (size_t)tap*DIM*DIM + (size_t)(k0+kk)*128 + c4*4);
        }
        As[0][qk*4+0][m]=rA.x; As[0][qk*4+1][m]=rA.y;
        As[0][qk*4+2][m]=rA.z; As[0][qk*4+3][m]=rA.w;
#pragma unroll
        for (int i = 0; i < 2; i++){
            int idx = tid + i*256;
            int c4 = idx & 31, kk = idx >> 5;
            *reinterpret_cast<float4*>(&Bs[0][kk][c4*4]) = rB[i];
        }
    }
    __syncthreads();

    for (int ch = 0; ch < 72; ch++){
        const int cur = ch & 1;
        const bool more = (ch + 1 < 72);
        if (more){
            const int tap = (ch+1) >> 3;
            const int k0  = ((ch+1) & 7) * 16;
            const int kh = tap/3 - 1, kw = tap%3 - 1;
            const int hi = 2*h + kh, wi = 2*w + kw;
            rA = make_float4(0.f,0.f,0.f,0.f);
            if ((unsigned)hi < HI && (unsigned)wi < WI)
                rA = *reinterpret_cast<const float4*>(
                      X + ((size_t)b*NPIX_IN + hi*WI + wi)*DIM + k0 + qk*4);
#pragma unroll
            for (int i = 0; i < 2; i++){
                int idx = tid + i*256;
                int c4 = idx & 31, kk = idx >> 5;
                rB[i] = *reinterpret_cast<const float4*>(
                         g_cwT + (size_t)tap*DIM*DIM + (size_t)(k0+kk)*128 + c4*4);
            }
        }
#pragma unroll
        for (int k = 0; k < 16; k++){
            float4 a0 = *reinterpret_cast<const float4*>(&As[cur][k][ty*4]);
            float4 b0 = *reinterpret_cast<const float4*>(&Bs[cur][k][tx*8]);
            float4 b1 = *reinterpret_cast<const float4*>(&Bs[cur][k][tx*8+4]);
            float av[4] = {a0.x,a0.y,a0.z,a0.w};
            float bv[8] = {b0.x,b0.y,b0.z,b0.w,b1.x,b1.y,b1.z,b1.w};
#pragma unroll
            for (int r = 0; r < 4; r++)
#pragma unroll
                for (int c = 0; c < 8; c++)
                    acc[r][c] += av[r]*bv[c];
        }
        if (more){
            const int nb = (ch+1) & 1;
            As[nb][qk*4+0][m]=rA.x; As[nb][qk*4+1][m]=rA.y;
            As[nb][qk*4+2][m]=rA.z; As[nb][qk*4+3][m]=rA.w;
#pragma unroll
            for (int i = 0; i < 2; i++){
                int idx = tid + i*256;
                int c4 = idx & 31, kk = idx >> 5;
                *reinterpret_cast<float4*>(&Bs[nb][kk][c4*4]) = rB[i];
            }
        }
        __syncthreads();
    }

    // epilogue: x_out = LN(seed); xln = LN(x_out)
    const int row0 = base + ty*4;
    const int c0 = tx*8;
    float gg[8], be[8];
#pragma unroll
    for (int c = 0; c < 8; c++){ gg[c] = lng[c0+c]; be[c] = lnb[c0+c]; }
#pragma unroll
    for (int r = 0; r < 4; r++){
        float v[8]; float s = 0.f;
#pragma unroll
        for (int c = 0; c < 8; c++){ v[c] = acc[r][c]; s += v[c]; }
        float mu = redsum16(s) * (1.0f/128.0f);
        float s2 = 0.f;
#pragma unroll
        for (int c = 0; c < 8; c++){ v[c] -= mu; s2 += v[c]*v[c]; }
        float rs = rsqrtf(redsum16(s2)*(1.0f/128.0f) + 1e-5f);
        float o[8];
#pragma unroll
        for (int c = 0; c < 8; c++) o[c] = v[c]*rs*gg[c] + be[c];
        float* op = g_xout + (size_t)(row0+r)*DIM + c0;
        reinterpret_cast<float4*>(op)[0] = make_float4(o[0],o[1],o[2],o[3]);
        reinterpret_cast<float4*>(op)[1] = make_float4(o[4],o[5],o[6],o[7]);
        float t = 0.f;
#pragma unroll
        for (int c = 0; c < 8; c++) t += o[c];
        float mu2 = redsum16(t) * (1.0f/128.0f);
        float t2 = 0.f;
#pragma unroll
        for (int c = 0; c < 8; c++){ o[c] -= mu2; t2 += o[c]*o[c]; }
        float rs2 = rsqrtf(redsum16(t2)*(1.0f/128.0f) + 1e-5f);
        float* xp = g_xln + (size_t)(row0+r)*DIM + c0;
        reinterpret_cast<float4*>(xp)[0] = make_float4(
            o[0]*rs2*gg[0]+be[0], o[1]*rs2*gg[1]+be[1],
            o[2]*rs2*gg[2]+be[2], o[3]*rs2*gg[3]+be[3]);
        reinterpret_cast<float4*>(xp)[1] = make_float4(
            o[4]*rs2*gg[4]+be[4], o[5]*rs2*gg[5]+be[5],
            o[6]*rs2*gg[6]+be[6], o[7]*rs2*gg[7]+be[7]);
    }
}

// ---------------- zero column sums -------------------------------------------
__global__ void zero_colsum_kernel(){
    g_colsum[blockIdx.x*blockDim.x + threadIdx.x] = 0.f;
}

// ---------------- attention: scores + softmax + eps + colsum atomics ---------
__global__ void attn_kernel(const float* __restrict__ rpb,
                            const float* __restrict__ tau,
                            float* __restrict__ attn_out)
{
    const int tid = threadIdx.x, warp = tid >> 5, lane = tid & 31;
    const int id  = blockIdx.x*4 + warp;
    const int b   = id >> 14;
    const int rem = id & 16383;
    const int g   = rem >> 12;
    const int hw  = rem & 4095;
    const int h = hw >> 6, w = hw & 63;
    const int ga = g >> 1, gb = g & 1;
    const int pix = (2*h + ga)*WI + 2*w + gb;
    const float4 kv = reinterpret_cast<const float4*>(g_k + ((size_t)b*NPIX_IN + pix)*DIM)[lane];
    const float scale = expf(tau[0]);
    const int ch = min(max(h,1), HO-2), cw = min(max(w,1), WO-2);

    float p[9];
    float m = -1e30f;
#pragma unroll
    for (int t = 0; t < 9; t++){
        const int nh = ch + t/3 - 1, nw = cw + t%3 - 1;
        const float4 q4 = reinterpret_cast<const float4*>(g_q + ((size_t)b*NPIX_OUT + nh*WO + nw)*DIM)[lane];
        float d = kv.x*q4.x + kv.y*q4.y + kv.z*q4.z + kv.w*q4.w;
        d = wredsum(d);
        const float val = (d + rpb[g*9 + t]) * scale;
        p[t] = val;
        m = fmaxf(m, val);
    }
    float s = 0.f;
#pragma unroll
    for (int t = 0; t < 9; t++){ p[t] = expf(p[t] - m); s += p[t]; }
    const float inv = 1.f/s;
#pragma unroll
    for (int t = 0; t < 9; t++) p[t] = p[t]*inv + 1e-6f;

    if (lane == 0){
        float* ao = attn_out + (size_t)id*9;
#pragma unroll
        for (int t = 0; t < 9; t++) ao[t] = p[t];
#pragma unroll
        for (int t = 0; t < 9; t++){
            const int nh = ch + t/3 - 1, nw = cw + t%3 - 1;
            atomicAdd(&g_colsum[b*NPIX_OUT + nh*WO + nw], p[t]);
        }
    }
}

// ---------------- normalized aggregation: A_col + upd + residual -------------
__global__ void upd_kernel(const float* __restrict__ attn_in,
                           float* __restrict__ acol_out)
{
    const int tid = threadIdx.x, warp = tid >> 5, lane = tid & 31;
    const int id = blockIdx.x*4 + warp;
    const int b  = id >> 12;
    const int hw = id & 4095;
    const int h = hw >> 6, w = hw & 63;
    const int ch = min(max(h,1), HO-2), cw = min(max(w,1), WO-2);

    float inv_dn[9];
#pragma unroll
    for (int t = 0; t < 9; t++){
        const int nh = ch + t/3 - 1, nw = cw + t%3 - 1;
        inv_dn[t] = 1.0f / (g_colsum[b*NPIX_OUT + nh*WO + nw] + 1e-8f);
    }
    float4 acc = make_float4(0.f,0.f,0.f,0.f);
#pragma unroll
    for (int g = 0; g < 4; g++){
        const int ga = g >> 1, gb = g & 1;
        const size_t base = ((size_t)((b*4 + g)*NPIX_OUT) + hw)*9;
        const float* ab = attn_in + base;
        float* cb = acol_out + base;
#pragma unroll
        for (int t = 0; t < 9; t++){
            const float coeff = ab[t] * inv_dn[t];
            if (lane == 0) cb[t] = coeff;
            const int nh = ch + t/3 - 1, nw = cw + t%3 - 1;
            const int pix = (2*nh + ga)*WI + 2*nw + gb;
            const float4 vv = reinterpret_cast<const float4*>(g_v + ((size_t)b*NPIX_IN + pix)*DIM)[lane];
            acc.x += coeff*vv.x; acc.y += coeff*vv.y; acc.z += coeff*vv.z; acc.w += coeff*vv.w;
        }
    }
    float4* xo = reinterpret_cast<float4*>(g_xout + (size_t)id*DIM);
    float4 v = xo[lane];
    v.x += acc.x; v.y += acc.y; v.z += acc.z; v.w += acc.w;
    xo[lane] = v;
}

// ---------------- launch ------------------------------------------------------
extern "C" void kernel_launch(void* const* d_in, const int* in_sizes, int n_in,
                              void* d_out, int out_size)
{
    const float* x      = (const float*)d_in[0];
    const float* convw  = (const float*)d_in[1];
    const float* q_w    = (const float*)d_in[2];
    const float* k_w    = (const float*)d_in[3];
    const float* v_w    = (const float*)d_in[4];
    const float* w1     = (const float*)d_in[5];
    const float* b1     = (const float*)d_in[6];
    const float* w2     = (const float*)d_in[7];
    const float* b2     = (const float*)d_in[8];
    const float* lin_g  = (const float*)d_in[9];
    const float* lin_b  = (const float*)d_in[10];
    const float* lout_g = (const float*)d_in[11];
    const float* lout_b = (const float*)d_in[12];
    const float* tau    = (const float*)d_in[13];
    const float* rpb    = (const float*)d_in[14];

    float* out      = (float*)d_out;
    float* out_x    = out;                                        // (4,4096,128)
    float* out_attn = out + (size_t)NROWS_OUT*DIM;                // (4,4,64,64,9)
    float* out_acol = out_attn + (size_t)BATCH*4*NPIX_OUT*9;      // (4,4,64,64,9)

    float *pk, *pv, *pq, *pxout, *pxln, *ph;
    cudaGetSymbolAddress((void**)&pk,    g_k);
    cudaGetSymbolAddress((void**)&pv,    g_v);
    cudaGetSymbolAddress((void**)&pq,    g_q);
    cudaGetSymbolAddress((void**)&pxout, g_xout);
    cudaGetSymbolAddress((void**)&pxln,  g_xln);
    cudaGetSymbolAddress((void**)&ph,    g_h);

    // preprocessing
    transpose_cw_kernel<<<(9*DIM*DIM + 255)/256, 256>>>(convw);
    ln_kernel<<<NROWS_IN/8, 256>>>(x, pxln, lin_g, lin_b);
    gemm_kernel<128,8><<<NROWS_IN/128, 256>>>(pxln, 128, k_w, 128, nullptr, nullptr, nullptr,
                                              pk, 128, nullptr, nullptr, nullptr, EPI_STORE, 0);
    gemm_kernel<128,8><<<NROWS_IN/128, 256>>>(x,    128, v_w, 128, nullptr, nullptr, nullptr,
                                              pv, 128, nullptr, nullptr, nullptr, EPI_STORE, 0);
    conv_kernel<<<NROWS_OUT/64, 256>>>(x, lout_g, lout_b);

    for (int it = 0; it < 3; it++){
        zero_colsum_kernel<<<(BATCH*NPIX_OUT)/256, 256>>>();
        gemm_kernel<64,4><<<NROWS_OUT/64, 256>>>(pxln, 128, q_w, 128, nullptr, nullptr, nullptr,
                                                 pq, 128, nullptr, nullptr, nullptr, EPI_STORE, 0);
        attn_kernel<<<(BATCH*4*NPIX_OUT)/4, 128>>>(rpb, tau, out_attn);
        upd_kernel<<<NROWS_OUT/4, 128>>>(out_attn, out_acol);
        gemm_kernel<64,4><<<dim3(NROWS_OUT/64, 2), 256>>>(pxout, 128, w1, 256, b1, nullptr, nullptr,
                                                          ph, 256, nullptr, nullptr, nullptr, EPI_GELU, 0);
        gemm_kernel<64,4><<<NROWS_OUT/64, 256>>>(ph, 256, w2, 128, b2, lout_g, lout_b,
                                                 nullptr, 128, pxout, out_x, pxln,
                                                 EPI_LNRES, it == 2 ? 1 : 0);
    }
    (void)in_sizes; (void)n_in; (void)out_size;
}

// round 6
// speedup vs baseline: 1.1452x; 1.1452x over previous
#include <cuda_runtime.h>
#include <math.h>

#define BATCH 4
#define HI 128
#define WI 128
#define HO 64
#define WO 64
#define DIM 128
#define NPIX_IN  (HI*WI)        // 16384
#define NPIX_OUT (HO*WO)        // 4096
#define NROWS_IN  (BATCH*NPIX_IN)   // 65536
#define NROWS_OUT (BATCH*NPIX_OUT)  // 16384

// ---------------- scratch (device globals) ----------------------------------
__device__ float g_cwT[9*DIM*DIM];                       // conv weights [tap][i][o]
__device__ float g_k   [(size_t)NROWS_IN*DIM];
__device__ float g_v   [(size_t)NROWS_IN*DIM];
__device__ float g_xln [(size_t)NROWS_IN*DIM];           // LN-ed activations
__device__ float g_xout[(size_t)NROWS_OUT*DIM];
__device__ float g_q   [(size_t)NROWS_OUT*DIM];
__device__ float g_h   [(size_t)NROWS_OUT*2*DIM];
__device__ float g_colsum[BATCH*NPIX_OUT];

// ---------------- helpers ----------------------------------------------------
static __device__ __forceinline__ float wredsum(float v){
#pragma unroll
    for (int o = 16; o > 0; o >>= 1) v += __shfl_xor_sync(0xffffffffu, v, o);
    return v;
}
static __device__ __forceinline__ float redsum16(float v){
#pragma unroll
    for (int o = 8; o > 0; o >>= 1) v += __shfl_xor_sync(0xffffffffu, v, o);
    return v;
}
static __device__ __forceinline__ float geluf(float x){
    return 0.5f * x * (1.0f + erff(x * 0.70710678118654752440f));
}
static __device__ __forceinline__ void cp16(float* dst, const float* src){
    unsigned s = (unsigned)__cvta_generic_to_shared(dst);
    asm volatile("cp.async.cg.shared.global [%0], [%1], 16;" :: "r"(s), "l"(src));
}
static __device__ __forceinline__ void cp_commit(){
    asm volatile("cp.async.commit_group;");
}
template<int N>
static __device__ __forceinline__ void cp_wait(){
    asm volatile("cp.async.wait_group %0;" :: "n"(N));
}

// ---------------- conv weight transpose: [o][i][kh][kw] -> [tap][i][o] -------
__global__ void transpose_cw_kernel(const float* __restrict__ cw){
    int idx = blockIdx.x * blockDim.x + threadIdx.x;
    if (idx >= 9*DIM*DIM) return;
    int o   = idx / (DIM*9);
    int rem = idx - o*(DIM*9);
    int i   = rem / 9;
    int tap = rem - i*9;
    g_cwT[(size_t)tap*DIM*DIM + i*DIM + o] = cw[idx];
}

// ---------------- standalone LayerNorm (warp per row) ------------------------
__global__ void __launch_bounds__(256) ln_kernel(
    const float* __restrict__ in, float* __restrict__ out,
    const float* __restrict__ g, const float* __restrict__ b)
{
    const int lane = threadIdx.x & 31, warp = threadIdx.x >> 5;
    const int row = blockIdx.x*8 + warp;
    float4 v = reinterpret_cast<const float4*>(in + (size_t)row*DIM)[lane];
    float mu = wredsum(v.x+v.y+v.z+v.w) * (1.0f/DIM);
    float dx=v.x-mu, dy=v.y-mu, dz=v.z-mu, dw=v.w-mu;
    float var = wredsum(dx*dx+dy*dy+dz*dz+dw*dw) * (1.0f/DIM);
    float rs = rsqrtf(var + 1e-5f);
    float4 gg = reinterpret_cast<const float4*>(g)[lane];
    float4 bb = reinterpret_cast<const float4*>(b)[lane];
    float4 o;
    o.x = dx*rs*gg.x + bb.x; o.y = dy*rs*gg.y + bb.y;
    o.z = dz*rs*gg.z + bb.z; o.w = dw*rs*gg.w + bb.w;
    reinterpret_cast<float4*>(out + (size_t)row*DIM)[lane] = o;
}

// ---------------- 3-stage pipelined SGEMM: 128x128 tile, BK=32, 8x8 micro ---
// A via LDG->reg->transposed STS (one chunk ahead); B via cp.async.cg (two ahead).
// One __syncthreads per chunk.
#define EPI_STORE 0
#define EPI_GELU  1
#define EPI_LNRES 2

#define AS_STRIDE 132
#define AS_STAGE  (32*AS_STRIDE)
#define BS_STAGE  (32*128)
#define SMEM_GEMM ((3*AS_STAGE + 3*BS_STAGE) * (int)sizeof(float))

__global__ void __launch_bounds__(256,2) gemm_kernel(
    const float* __restrict__ A, int K,
    const float* __restrict__ B, int ldb,
    const float* __restrict__ bias,
    const float* __restrict__ lng, const float* __restrict__ lnb,
    float* __restrict__ C, int ldc,
    float* __restrict__ res, float* __restrict__ fin, float* __restrict__ xln,
    int epi, int writeFinal)
{
    extern __shared__ float sm[];
    float* As = sm;                    // 3 stages of [32][132]
    float* Bs = sm + 3*AS_STAGE;       // 3 stages of [32][128]
    const int tid = threadIdx.x;
    const int tx = tid & 15, ty = tid >> 4;
    const int mBase = blockIdx.x * 128;
    const int col0  = blockIdx.y * 128;

    const int am  = tid & 127;         // A: pixel row this thread loads
    const int aq0 = tid >> 7;          // A: base k-quad (0 or 1)
    const int bc4 = tid & 31;          // B: float4 column
    const int bk0 = tid >> 5;          // B: base k-row (0..7)

    float acc[8][8];
#pragma unroll
    for (int r = 0; r < 8; r++)
#pragma unroll
        for (int c = 0; c < 8; c++) acc[r][c] = 0.f;

    const int nCh = K >> 5;            // >= 4 always
    float4 rA[4];

    const float* Arow = A + (size_t)(mBase + am)*K;

    // prologue: stage 0 fully, stage 1 loads in flight
#pragma unroll
    for (int i = 0; i < 4; i++)
        rA[i] = *reinterpret_cast<const float4*>(Arow + (aq0 + i*2)*4);
#pragma unroll
    for (int i = 0; i < 4; i++){
        int kk = bk0 + i*8;
        cp16(Bs + 0*BS_STAGE + kk*128 + bc4*4, B + (size_t)kk*ldb + col0 + bc4*4);
    }
    cp_commit();
    {
        float* ab = As + 0*AS_STAGE;
#pragma unroll
        for (int i = 0; i < 4; i++){
            int q = aq0 + i*2;
            ab[(q*4+0)*AS_STRIDE + am] = rA[i].x;
            ab[(q*4+1)*AS_STRIDE + am] = rA[i].y;
            ab[(q*4+2)*AS_STRIDE + am] = rA[i].z;
            ab[(q*4+3)*AS_STRIDE + am] = rA[i].w;
        }
    }
#pragma unroll
    for (int i = 0; i < 4; i++)
        rA[i] = *reinterpret_cast<const float4*>(Arow + 32 + (aq0 + i*2)*4);
#pragma unroll
    for (int i = 0; i < 4; i++){
        int kk = bk0 + i*8;
        cp16(Bs + 1*BS_STAGE + kk*128 + bc4*4, B + (size_t)(32+kk)*ldb + col0 + bc4*4);
    }
    cp_commit();

    for (int ch = 0; ch < nCh; ch++){
        // STS the A chunk (ch+1) staged in registers
        if (ch + 1 < nCh){
            float* ab = As + ((ch+1)%3)*AS_STAGE;
#pragma unroll
            for (int i = 0; i < 4; i++){
                int q = aq0 + i*2;
                ab[(q*4+0)*AS_STRIDE + am] = rA[i].x;
                ab[(q*4+1)*AS_STRIDE + am] = rA[i].y;
                ab[(q*4+2)*AS_STRIDE + am] = rA[i].z;
                ab[(q*4+3)*AS_STRIDE + am] = rA[i].w;
            }
        }
        cp_wait<1>();
        __syncthreads();
        // issue loads for chunk ch+2 (after barrier: safe to overwrite stage)
        if (ch + 2 < nCh){
            const int k0 = (ch+2) << 5;
#pragma unroll
            for (int i = 0; i < 4; i++)
                rA[i] = *reinterpret_cast<const float4*>(Arow + k0 + (aq0 + i*2)*4);
            float* bbst = Bs + ((ch+2)%3)*BS_STAGE;
#pragma unroll
            for (int i = 0; i < 4; i++){
                int kk = bk0 + i*8;
                cp16(bbst + kk*128 + bc4*4, B + (size_t)(k0+kk)*ldb + col0 + bc4*4);
            }
        }
        cp_commit();
        // compute chunk ch
        const float* ab = As + (ch%3)*AS_STAGE;
        const float* bb = Bs + (ch%3)*BS_STAGE;
#pragma unroll
        for (int k = 0; k < 32; k++){
            float4 a0 = *reinterpret_cast<const float4*>(ab + k*AS_STRIDE + ty*8);
            float4 a1 = *reinterpret_cast<const float4*>(ab + k*AS_STRIDE + ty*8 + 4);
            float4 b0 = *reinterpret_cast<const float4*>(bb + k*128 + tx*8);
            float4 b1 = *reinterpret_cast<const float4*>(bb + k*128 + tx*8 + 4);
            float av[8] = {a0.x,a0.y,a0.z,a0.w,a1.x,a1.y,a1.z,a1.w};
            float bv[8] = {b0.x,b0.y,b0.z,b0.w,b1.x,b1.y,b1.z,b1.w};
#pragma unroll
            for (int r = 0; r < 8; r++)
#pragma unroll
                for (int c = 0; c < 8; c++)
                    acc[r][c] += av[r]*bv[c];
        }
    }

    const int row0 = mBase + ty*8;
    const int c0   = col0 + tx*8;

    if (epi == EPI_STORE){
#pragma unroll
        for (int r = 0; r < 8; r++){
            float4* cp = reinterpret_cast<float4*>(C + (size_t)(row0+r)*ldc + c0);
            cp[0] = make_float4(acc[r][0],acc[r][1],acc[r][2],acc[r][3]);
            cp[1] = make_float4(acc[r][4],acc[r][5],acc[r][6],acc[r][7]);
        }
    } else if (epi == EPI_GELU){
        float bb[8];
#pragma unroll
        for (int c = 0; c < 8; c++) bb[c] = bias[c0+c];
#pragma unroll
        for (int r = 0; r < 8; r++){
            float v[8];
#pragma unroll
            for (int c = 0; c < 8; c++) v[c] = geluf(acc[r][c] + bb[c]);
            float4* cp = reinterpret_cast<float4*>(C + (size_t)(row0+r)*ldc + c0);
            cp[0] = make_float4(v[0],v[1],v[2],v[3]);
            cp[1] = make_float4(v[4],v[5],v[6],v[7]);
        }
    } else { // EPI_LNRES: x_out += LN(acc + bias); xln = LN(new x_out)
        float bb[8], gg[8], be[8];
#pragma unroll
        for (int c = 0; c < 8; c++){
            bb[c] = bias[c0+c]; gg[c] = lng[c0+c]; be[c] = lnb[c0+c];
        }
#pragma unroll
        for (int r = 0; r < 8; r++){
            float v[8]; float s = 0.f;
#pragma unroll
            for (int c = 0; c < 8; c++){ v[c] = acc[r][c] + bb[c]; s += v[c]; }
            float mu = redsum16(s) * (1.0f/128.0f);
            float s2 = 0.f;
#pragma unroll
            for (int c = 0; c < 8; c++){ v[c] -= mu; s2 += v[c]*v[c]; }
            float rs = rsqrtf(redsum16(s2)*(1.0f/128.0f) + 1e-5f);
            float* rp = res + (size_t)(row0+r)*DIM + c0;
            float o[8];
#pragma unroll
            for (int c = 0; c < 8; c++) o[c] = rp[c] + v[c]*rs*gg[c] + be[c];
            reinterpret_cast<float4*>(rp)[0] = make_float4(o[0],o[1],o[2],o[3]);
            reinterpret_cast<float4*>(rp)[1] = make_float4(o[4],o[5],o[6],o[7]);
            if (writeFinal){
                float* fp = fin + (size_t)(row0+r)*DIM + c0;
                reinterpret_cast<float4*>(fp)[0] = make_float4(o[0],o[1],o[2],o[3]);
                reinterpret_cast<float4*>(fp)[1] = make_float4(o[4],o[5],o[6],o[7]);
            }
            float t = 0.f;
#pragma unroll
            for (int c = 0; c < 8; c++) t += o[c];
            float mu2 = redsum16(t) * (1.0f/128.0f);
            float t2 = 0.f;
#pragma unroll
            for (int c = 0; c < 8; c++){ o[c] -= mu2; t2 += o[c]*o[c]; }
            float rs2 = rsqrtf(redsum16(t2)*(1.0f/128.0f) + 1e-5f);
            float* xp = xln + (size_t)(row0+r)*DIM + c0;
            reinterpret_cast<float4*>(xp)[0] = make_float4(
                o[0]*rs2*gg[0]+be[0], o[1]*rs2*gg[1]+be[1],
                o[2]*rs2*gg[2]+be[2], o[3]*rs2*gg[3]+be[3]);
            reinterpret_cast<float4*>(xp)[1] = make_float4(
                o[4]*rs2*gg[4]+be[4], o[5]*rs2*gg[5]+be[5],
                o[6]*rs2*gg[6]+be[6], o[7]*rs2*gg[7]+be[7]);
        }
    }
}

// ---------------- conv as tap-looped SGEMM + dual-LN epilogue ----------------
// 64 out-pixels x 128 out-channels per block; 256 threads; 4x8 micro-tile.
__global__ void __launch_bounds__(256) conv_kernel(
    const float* __restrict__ X,
    const float* __restrict__ lng, const float* __restrict__ lnb)
{
    __shared__ __align__(16) float As[32*68];
    __shared__ __align__(16) float Bs[32*128];
    const int tid = threadIdx.x;
    const int tx = tid & 15, ty = tid >> 4;
    const int base = blockIdx.x * 64;     // out-pixel base (same batch)
    const int b = base >> 12;

    float acc[4][8];
#pragma unroll
    for (int r = 0; r < 4; r++)
#pragma unroll
        for (int c = 0; c < 8; c++) acc[r][c] = 0.f;

    for (int ch = 0; ch < 36; ch++){
        const int tap = ch >> 2;
        const int k0  = (ch & 3) * 32;
        const int kh = tap/3 - 1, kw = tap%3 - 1;
#pragma unroll
        for (int i = 0; i < 2; i++){
            int idx = tid + i*256;
            int m = idx & 63, q = idx >> 6;
            int hw = (base + m) & 4095;
            int h = hw >> 6, w = hw & 63;
            int hi = 2*h + kh, wi = 2*w + kw;
            float4 a = make_float4(0.f,0.f,0.f,0.f);
            if ((unsigned)hi < HI && (unsigned)wi < WI)
                a = *reinterpret_cast<const float4*>(
                      X + ((size_t)b*NPIX_IN + hi*WI + wi)*DIM + k0 + q*4);
            As[(q*4+0)*68 + m] = a.x;
            As[(q*4+1)*68 + m] = a.y;
            As[(q*4+2)*68 + m] = a.z;
            As[(q*4+3)*68 + m] = a.w;
        }
#pragma unroll
        for (int i = 0; i < 4; i++){
            int idx = tid + i*256;
            int c4 = idx & 31, kk = idx >> 5;
            *reinterpret_cast<float4*>(Bs + kk*128 + c4*4) =
                *reinterpret_cast<const float4*>(g_cwT + (size_t)tap*DIM*DIM + (k0+kk)*128 + c4*4);
        }
        __syncthreads();
#pragma unroll 8
        for (int k = 0; k < 32; k++){
            float4 a0 = *reinterpret_cast<float4*>(As + k*68 + ty*4);
            float4 b0 = *reinterpret_cast<float4*>(Bs + k*128 + tx*8);
            float4 b1 = *reinterpret_cast<float4*>(Bs + k*128 + tx*8 + 4);
            float av[4] = {a0.x,a0.y,a0.z,a0.w};
            float bv[8] = {b0.x,b0.y,b0.z,b0.w,b1.x,b1.y,b1.z,b1.w};
#pragma unroll
            for (int r = 0; r < 4; r++)
#pragma unroll
                for (int c = 0; c < 8; c++)
                    acc[r][c] += av[r]*bv[c];
        }
        __syncthreads();
    }

    // epilogue: x_out = LN(seed); xln = LN(x_out)
    const int row0 = base + ty*4;
    const int c0 = tx*8;
    float gg[8], be[8];
#pragma unroll
    for (int c = 0; c < 8; c++){ gg[c] = lng[c0+c]; be[c] = lnb[c0+c]; }
#pragma unroll
    for (int r = 0; r < 4; r++){
        float v[8]; float s = 0.f;
#pragma unroll
        for (int c = 0; c < 8; c++){ v[c] = acc[r][c]; s += v[c]; }
        float mu = redsum16(s) * (1.0f/128.0f);
        float s2 = 0.f;
#pragma unroll
        for (int c = 0; c < 8; c++){ v[c] -= mu; s2 += v[c]*v[c]; }
        float rs = rsqrtf(redsum16(s2)*(1.0f/128.0f) + 1e-5f);
        float o[8];
#pragma unroll
        for (int c = 0; c < 8; c++) o[c] = v[c]*rs*gg[c] + be[c];
        float* op = g_xout + (size_t)(row0+r)*DIM + c0;
        reinterpret_cast<float4*>(op)[0] = make_float4(o[0],o[1],o[2],o[3]);
        reinterpret_cast<float4*>(op)[1] = make_float4(o[4],o[5],o[6],o[7]);
        float t = 0.f;
#pragma unroll
        for (int c = 0; c < 8; c++) t += o[c];
        float mu2 = redsum16(t) * (1.0f/128.0f);
        float t2 = 0.f;
#pragma unroll
        for (int c = 0; c < 8; c++){ o[c] -= mu2; t2 += o[c]*o[c]; }
        float rs2 = rsqrtf(redsum16(t2)*(1.0f/128.0f) + 1e-5f);
        float* xp = g_xln + (size_t)(row0+r)*DIM + c0;
        reinterpret_cast<float4*>(xp)[0] = make_float4(
            o[0]*rs2*gg[0]+be[0], o[1]*rs2*gg[1]+be[1],
            o[2]*rs2*gg[2]+be[2], o[3]*rs2*gg[3]+be[3]);
        reinterpret_cast<float4*>(xp)[1] = make_float4(
            o[4]*rs2*gg[4]+be[4], o[5]*rs2*gg[5]+be[5],
            o[6]*rs2*gg[6]+be[6], o[7]*rs2*gg[7]+be[7]);
    }
}

// ---------------- zero column sums -------------------------------------------
__global__ void zero_colsum_kernel(){
    g_colsum[blockIdx.x*blockDim.x + threadIdx.x] = 0.f;
}

// ---------------- attention: scores + softmax + eps + colsum atomics ---------
__global__ void attn_kernel(const float* __restrict__ rpb,
                            const float* __restrict__ tau,
                            float* __restrict__ attn_out)
{
    const int tid = threadIdx.x, warp = tid >> 5, lane = tid & 31;
    const int id  = blockIdx.x*4 + warp;
    const int b   = id >> 14;
    const int rem = id & 16383;
    const int g   = rem >> 12;
    const int hw  = rem & 4095;
    const int h = hw >> 6, w = hw & 63;
    const int ga = g >> 1, gb = g & 1;
    const int pix = (2*h + ga)*WI + 2*w + gb;
    const float4 kv = reinterpret_cast<const float4*>(g_k + ((size_t)b*NPIX_IN + pix)*DIM)[lane];
    const float scale = expf(tau[0]);
    const int ch = min(max(h,1), HO-2), cw = min(max(w,1), WO-2);

    float p[9];
    float m = -1e30f;
#pragma unroll
    for (int t = 0; t < 9; t++){
        const int nh = ch + t/3 - 1, nw = cw + t%3 - 1;
        const float4 q4 = reinterpret_cast<const float4*>(g_q + ((size_t)b*NPIX_OUT + nh*WO + nw)*DIM)[lane];
        float d = kv.x*q4.x + kv.y*q4.y + kv.z*q4.z + kv.w*q4.w;
        d = wredsum(d);
        const float val = (d + rpb[g*9 + t]) * scale;
        p[t] = val;
        m = fmaxf(m, val);
    }
    float s = 0.f;
#pragma unroll
    for (int t = 0; t < 9; t++){ p[t] = expf(p[t] - m); s += p[t]; }
    const float inv = 1.f/s;
#pragma unroll
    for (int t = 0; t < 9; t++) p[t] = p[t]*inv + 1e-6f;

    if (lane == 0){
        float* ao = attn_out + (size_t)id*9;
#pragma unroll
        for (int t = 0; t < 9; t++) ao[t] = p[t];
#pragma unroll
        for (int t = 0; t < 9; t++){
            const int nh = ch + t/3 - 1, nw = cw + t%3 - 1;
            atomicAdd(&g_colsum[b*NPIX_OUT + nh*WO + nw], p[t]);
        }
    }
}

// ---------------- normalized aggregation: A_col + upd + residual -------------
__global__ void upd_kernel(const float* __restrict__ attn_in,
                           float* __restrict__ acol_out)
{
    const int tid = threadIdx.x, warp = tid >> 5, lane = tid & 31;
    const int id = blockIdx.x*4 + warp;
    const int b  = id >> 12;
    const int hw = id & 4095;
    const int h = hw >> 6, w = hw & 63;
    const int ch = min(max(h,1), HO-2), cw = min(max(w,1), WO-2);

    float inv_dn[9];
#pragma unroll
    for (int t = 0; t < 9; t++){
        const int nh = ch + t/3 - 1, nw = cw + t%3 - 1;
        inv_dn[t] = 1.0f / (g_colsum[b*NPIX_OUT + nh*WO + nw] + 1e-8f);
    }
    float4 acc = make_float4(0.f,0.f,0.f,0.f);
#pragma unroll
    for (int g = 0; g < 4; g++){
        const int ga = g >> 1, gb = g & 1;
        const size_t base = ((size_t)((b*4 + g)*NPIX_OUT) + hw)*9;
        const float* ab = attn_in + base;
        float* cb = acol_out + base;
#pragma unroll
        for (int t = 0; t < 9; t++){
            const float coeff = ab[t] * inv_dn[t];
            if (lane == 0) cb[t] = coeff;
            const int nh = ch + t/3 - 1, nw = cw + t%3 - 1;
            const int pix = (2*nh + ga)*WI + 2*nw + gb;
            const float4 vv = reinterpret_cast<const float4*>(g_v + ((size_t)b*NPIX_IN + pix)*DIM)[lane];
            acc.x += coeff*vv.x; acc.y += coeff*vv.y; acc.z += coeff*vv.z; acc.w += coeff*vv.w;
        }
    }
    float4* xo = reinterpret_cast<float4*>(g_xout + (size_t)id*DIM);
    float4 v = xo[lane];
    v.x += acc.x; v.y += acc.y; v.z += acc.z; v.w += acc.w;
    xo[lane] = v;
}

// ---------------- launch ------------------------------------------------------
extern "C" void kernel_launch(void* const* d_in, const int* in_sizes, int n_in,
                              void* d_out, int out_size)
{
    const float* x      = (const float*)d_in[0];
    const float* convw  = (const float*)d_in[1];
    const float* q_w    = (const float*)d_in[2];
    const float* k_w    = (const float*)d_in[3];
    const float* v_w    = (const float*)d_in[4];
    const float* w1     = (const float*)d_in[5];
    const float* b1     = (const float*)d_in[6];
    const float* w2     = (const float*)d_in[7];
    const float* b2     = (const float*)d_in[8];
    const float* lin_g  = (const float*)d_in[9];
    const float* lin_b  = (const float*)d_in[10];
    const float* lout_g = (const float*)d_in[11];
    const float* lout_b = (const float*)d_in[12];
    const float* tau    = (const float*)d_in[13];
    const float* rpb    = (const float*)d_in[14];

    float* out      = (float*)d_out;
    float* out_x    = out;                                        // (4,4096,128)
    float* out_attn = out + (size_t)NROWS_OUT*DIM;                // (4,4,64,64,9)
    float* out_acol = out_attn + (size_t)BATCH*4*NPIX_OUT*9;      // (4,4,64,64,9)

    float *pk, *pv, *pq, *pxout, *pxln, *ph;
    cudaGetSymbolAddress((void**)&pk,    g_k);
    cudaGetSymbolAddress((void**)&pv,    g_v);
    cudaGetSymbolAddress((void**)&pq,    g_q);
    cudaGetSymbolAddress((void**)&pxout, g_xout);
    cudaGetSymbolAddress((void**)&pxln,  g_xln);
    cudaGetSymbolAddress((void**)&ph,    g_h);

    cudaFuncSetAttribute(gemm_kernel, cudaFuncAttributeMaxDynamicSharedMemorySize, SMEM_GEMM);

    // preprocessing
    transpose_cw_kernel<<<(9*DIM*DIM + 255)/256, 256>>>(convw);
    ln_kernel<<<NROWS_IN/8, 256>>>(x, pxln, lin_g, lin_b);
    gemm_kernel<<<NROWS_IN/128, 256, SMEM_GEMM>>>(pxln, 128, k_w, 128, nullptr, nullptr, nullptr,
                                                  pk, 128, nullptr, nullptr, nullptr, EPI_STORE, 0);
    gemm_kernel<<<NROWS_IN/128, 256, SMEM_GEMM>>>(x,    128, v_w, 128, nullptr, nullptr, nullptr,
                                                  pv, 128, nullptr, nullptr, nullptr, EPI_STORE, 0);
    conv_kernel<<<NROWS_OUT/64, 256>>>(x, lout_g, lout_b);

    for (int it = 0; it < 3; it++){
        zero_colsum_kernel<<<(BATCH*NPIX_OUT)/256, 256>>>();
        gemm_kernel<<<NROWS_OUT/128, 256, SMEM_GEMM>>>(pxln, 128, q_w, 128, nullptr, nullptr, nullptr,
                                                       pq, 128, nullptr, nullptr, nullptr, EPI_STORE, 0);
        attn_kernel<<<(BATCH*4*NPIX_OUT)/4, 128>>>(rpb, tau, out_attn);
        upd_kernel<<<NROWS_OUT/4, 128>>>(out_attn, out_acol);
        gemm_kernel<<<dim3(NROWS_OUT/128, 2), 256, SMEM_GEMM>>>(pxout, 128, w1, 256, b1, nullptr, nullptr,
                                                                ph, 256, nullptr, nullptr, nullptr, EPI_GELU, 0);
        gemm_kernel<<<NROWS_OUT/128, 256, SMEM_GEMM>>>(ph, 256, w2, 128, b2, lout_g, lout_b,
                                                       nullptr, 128, pxout, out_x, pxln,
                                                       EPI_LNRES, it == 2 ? 1 : 0);
    }
    (void)in_sizes; (void)n_in; (void)out_size;
}

// round 10
// speedup vs baseline: 1.3587x; 1.1864x over previous
#include <cuda_runtime.h>
#include <cuda_bf16.h>
#include <math.h>
#include <stdint.h>

#define BATCH 4
#define HI 128
#define WI 128
#define HO 64
#define WO 64
#define DIM 128
#define NPIX_IN  (HI*WI)
#define NPIX_OUT (HO*WO)
#define NROWS_IN  (BATCH*NPIX_IN)   // 65536
#define NROWS_OUT (BATCH*NPIX_OUT)  // 16384

// ---------------- scratch (device globals) ----------------------------------
__device__ float g_cwT[9*DIM*DIM];
__device__ float g_k   [(size_t)NROWS_IN*DIM];
__device__ float g_v   [(size_t)NROWS_IN*DIM];
__device__ float g_q   [(size_t)NROWS_OUT*DIM];
__device__ float g_xout[(size_t)NROWS_OUT*DIM];
__device__ float g_colsum[BATCH*NPIX_OUT];

// bf16 split buffers (hi/lo)
__device__ __align__(16) __nv_bfloat16 g_x_h  [(size_t)NROWS_IN*DIM];
__device__ __align__(16) __nv_bfloat16 g_x_l  [(size_t)NROWS_IN*DIM];
__device__ __align__(16) __nv_bfloat16 g_xli_h[(size_t)NROWS_IN*DIM];   // LN_in(x)
__device__ __align__(16) __nv_bfloat16 g_xli_l[(size_t)NROWS_IN*DIM];
__device__ __align__(16) __nv_bfloat16 g_xo_h [(size_t)NROWS_OUT*DIM];  // xout (post-upd)
__device__ __align__(16) __nv_bfloat16 g_xo_l [(size_t)NROWS_OUT*DIM];
__device__ __align__(16) __nv_bfloat16 g_xq_h [(size_t)NROWS_OUT*DIM];  // LN(xout)
__device__ __align__(16) __nv_bfloat16 g_xq_l [(size_t)NROWS_OUT*DIM];
__device__ __align__(16) __nv_bfloat16 g_hh_h [(size_t)NROWS_OUT*2*DIM];
__device__ __align__(16) __nv_bfloat16 g_hh_l [(size_t)NROWS_OUT*2*DIM];
// transposed-split weights [N,K]
__device__ __align__(16) __nv_bfloat16 g_wq_h[DIM*DIM], g_wq_l[DIM*DIM];
__device__ __align__(16) __nv_bfloat16 g_wk_h[DIM*DIM], g_wk_l[DIM*DIM];
__device__ __align__(16) __nv_bfloat16 g_wv_h[DIM*DIM], g_wv_l[DIM*DIM];
__device__ __align__(16) __nv_bfloat16 g_w1_h[2*DIM*DIM], g_w1_l[2*DIM*DIM]; // [256,128]
__device__ __align__(16) __nv_bfloat16 g_w2_h[2*DIM*DIM], g_w2_l[2*DIM*DIM]; // [128,256]

// ---------------- helpers ----------------------------------------------------
static __device__ __forceinline__ float wredsum(float v){
#pragma unroll
    for (int o = 16; o > 0; o >>= 1) v += __shfl_xor_sync(0xffffffffu, v, o);
    return v;
}
static __device__ __forceinline__ float redsum16(float v){
#pragma unroll
    for (int o = 8; o > 0; o >>= 1) v += __shfl_xor_sync(0xffffffffu, v, o);
    return v;
}
static __device__ __forceinline__ float geluf(float x){
    return 0.5f * x * (1.0f + erff(x * 0.70710678118654752440f));
}
static __device__ __forceinline__ uint32_t smem_u32(const void* p){
    uint32_t a;
    asm("{ .reg .u64 t; cvta.to.shared.u64 t, %1; cvt.u32.u64 %0, t; }" : "=r"(a) : "l"(p));
    return a;
}
static __device__ __forceinline__ void split2(float v, __nv_bfloat16& h, __nv_bfloat16& l){
    h = __float2bfloat16(v);
    l = __float2bfloat16(v - __bfloat162float(h));
}
static __device__ __forceinline__ void split_store4(
    __nv_bfloat16* ph, __nv_bfloat16* pl, const float* v)
{
    __nv_bfloat16 h[4], l[4];
#pragma unroll
    for (int i = 0; i < 4; i++) split2(v[i], h[i], l[i]);
    *reinterpret_cast<uint2*>(ph) = *reinterpret_cast<const uint2*>(h);
    *reinterpret_cast<uint2*>(pl) = *reinterpret_cast<const uint2*>(l);
}
static __device__ __forceinline__ void split_store8(
    __nv_bfloat16* ph, __nv_bfloat16* pl, const float* v)
{
    __nv_bfloat16 h[8], l[8];
#pragma unroll
    for (int i = 0; i < 8; i++) split2(v[i], h[i], l[i]);
    *reinterpret_cast<uint4*>(ph) = *reinterpret_cast<const uint4*>(h);
    *reinterpret_cast<uint4*>(pl) = *reinterpret_cast<const uint4*>(l);
}

// ---------------- mma primitives (baseline PTX: sm_80-compatible) -----------
static __device__ __forceinline__ void ldsm_x4(uint32_t* r, uint32_t addr){
    asm volatile("ldmatrix.sync.aligned.m8n8.x4.shared.b16 {%0,%1,%2,%3}, [%4];"
        : "=r"(r[0]), "=r"(r[1]), "=r"(r[2]), "=r"(r[3]) : "r"(addr));
}
static __device__ __forceinline__ void mma16816(
    float* c, const uint32_t* a, uint32_t b0, uint32_t b1)
{
    asm volatile(
        "mma.sync.aligned.m16n8k16.row.col.f32.bf16.bf16.f32 "
        "{%0,%1,%2,%3}, {%4,%5,%6,%7}, {%8,%9}, {%0,%1,%2,%3};"
        : "+f"(c[0]), "+f"(c[1]), "+f"(c[2]), "+f"(c[3])
        : "r"(a[0]), "r"(a[1]), "r"(a[2]), "r"(a[3]), "r"(b0), "r"(b1));
}

// ---------------- bf16-3x tensor-core GEMM -----------------------------------
// D[128 tile, 128 tile] = A @ B^T; A[M,Ktot] hi/lo, B[N,Ktot] hi/lo (row-major).
// 8 warps in 4(M) x 2(N); warp tile 32x64; K chunked by 64 into padded smem.
#define EPI_STORE 0
#define EPI_GELU  1
#define EPI_LNRES 2

#define TSTRIDE 72                      // bf16 elements per smem row (pad 64->72)
#define TBYTES  (128*TSTRIDE*2)         // 18432 bytes per tile
#define OFF_AH  0
#define OFF_AL  (TBYTES)
#define OFF_BH  (2*TBYTES)
#define OFF_BL  (3*TBYTES)
#define SMEM_MMA (4*TBYTES)             // 73728

__global__ void __launch_bounds__(256) gemm_mma(
    const __nv_bfloat16* __restrict__ Ah, const __nv_bfloat16* __restrict__ Al, int Ktot,
    const __nv_bfloat16* __restrict__ Bh, const __nv_bfloat16* __restrict__ Bl,
    const float* __restrict__ bias,
    const float* __restrict__ lng, const float* __restrict__ lnb,
    float* __restrict__ C, int ldc,
    float* __restrict__ res, float* __restrict__ fin,
    __nv_bfloat16* __restrict__ ohi, __nv_bfloat16* __restrict__ olo, int ldo,
    int epi, int writeFinal)
{
    extern __shared__ char sm[];
    const uint32_t smb = smem_u32(sm);
    const int tid = threadIdx.x, wid = tid >> 5, lane = tid & 31;
    const int wm = wid & 3, wn = wid >> 2;
    const int mBase = blockIdx.x * 128;
    const int col0  = blockIdx.y * 128;

    float acc[2][8][4];
#pragma unroll
    for (int mt = 0; mt < 2; mt++)
#pragma unroll
        for (int nt = 0; nt < 8; nt++)
#pragma unroll
            for (int i = 0; i < 4; i++) acc[mt][nt][i] = 0.f;

    const __nv_bfloat16* Ah0 = Ah + (size_t)mBase*Ktot;
    const __nv_bfloat16* Al0 = Al + (size_t)mBase*Ktot;
    const __nv_bfloat16* Bh0 = Bh + (size_t)col0*Ktot;
    const __nv_bfloat16* Bl0 = Bl + (size_t)col0*Ktot;

    // ldmatrix lane addressing (element offsets within a tile)
    const int aRow = lane & 15, aKh = (lane >> 4) << 3;              // A: x4
    const int bRow = (lane & 7) + ((lane >> 4) << 3);                // B: x4
    const int bKh  = ((lane >> 3) & 1) << 3;

    for (int kc = 0; kc < Ktot; kc += 64){
        __syncthreads();
#pragma unroll
        for (int i = 0; i < 4; i++){
            int u = tid + i*256;
            int m = u >> 3, c8 = (u & 7) << 3;
            size_t go = (size_t)m*Ktot + kc + c8;
            int so = (m*TSTRIDE + c8) << 1;
            *reinterpret_cast<uint4*>(sm + OFF_AH + so) = *reinterpret_cast<const uint4*>(Ah0 + go);
            *reinterpret_cast<uint4*>(sm + OFF_AL + so) = *reinterpret_cast<const uint4*>(Al0 + go);
            *reinterpret_cast<uint4*>(sm + OFF_BH + so) = *reinterpret_cast<const uint4*>(Bh0 + go);
            *reinterpret_cast<uint4*>(sm + OFF_BL + so) = *reinterpret_cast<const uint4*>(Bl0 + go);
        }
        __syncthreads();

#pragma unroll
        for (int ks = 0; ks < 4; ks++){
            uint32_t ah[2][4], al[2][4];
#pragma unroll
            for (int mt = 0; mt < 2; mt++){
                const int eoff = ((wm*32 + mt*16 + aRow)*TSTRIDE + ks*16 + aKh) << 1;
                ldsm_x4(ah[mt], smb + OFF_AH + eoff);
                ldsm_x4(al[mt], smb + OFF_AL + eoff);
            }
#pragma unroll
            for (int np = 0; np < 4; np++){
                const int eoff = ((wn*64 + np*16 + bRow)*TSTRIDE + ks*16 + bKh) << 1;
                uint32_t bh4[4], bl4[4];
                ldsm_x4(bh4, smb + OFF_BH + eoff);
                ldsm_x4(bl4, smb + OFF_BL + eoff);
#pragma unroll
                for (int mt = 0; mt < 2; mt++){
#pragma unroll
                    for (int hf = 0; hf < 2; hf++){
                        float* c = acc[mt][np*2 + hf];
                        mma16816(c, ah[mt], bh4[hf*2], bh4[hf*2+1]);  // Ah*Bh
                        mma16816(c, al[mt], bh4[hf*2], bh4[hf*2+1]);  // Al*Bh
                        mma16816(c, ah[mt], bl4[hf*2], bl4[hf*2+1]);  // Ah*Bl
                    }
                }
            }
        }
    }

    // ---------------- epilogues ----------------
    if (epi == EPI_STORE){
#pragma unroll
        for (int mt = 0; mt < 2; mt++){
            const int row = mBase + wm*32 + mt*16 + (lane >> 2);
#pragma unroll
            for (int nt = 0; nt < 8; nt++){
                const int colg = col0 + wn*64 + nt*8 + ((lane & 3) << 1);
                *reinterpret_cast<float2*>(C + (size_t)row*ldc + colg) =
                    make_float2(acc[mt][nt][0], acc[mt][nt][1]);
                *reinterpret_cast<float2*>(C + (size_t)(row+8)*ldc + colg) =
                    make_float2(acc[mt][nt][2], acc[mt][nt][3]);
            }
        }
    } else if (epi == EPI_GELU){
#pragma unroll
        for (int mt = 0; mt < 2; mt++){
            const int row = mBase + wm*32 + mt*16 + (lane >> 2);
#pragma unroll
            for (int nt = 0; nt < 8; nt++){
                const int colg = col0 + wn*64 + nt*8 + ((lane & 3) << 1);
                const float b0 = bias[colg], b1 = bias[colg+1];
                float v0 = geluf(acc[mt][nt][0] + b0);
                float v1 = geluf(acc[mt][nt][1] + b1);
                float v2 = geluf(acc[mt][nt][2] + b0);
                float v3 = geluf(acc[mt][nt][3] + b1);
                __nv_bfloat16 h0,l0,h1,l1;
                split2(v0,h0,l0); split2(v1,h1,l1);
                *reinterpret_cast<__nv_bfloat162*>(ohi + (size_t)row*ldo + colg) = {h0,h1};
                *reinterpret_cast<__nv_bfloat162*>(olo + (size_t)row*ldo + colg) = {l0,l1};
                split2(v2,h0,l0); split2(v3,h1,l1);
                *reinterpret_cast<__nv_bfloat162*>(ohi + (size_t)(row+8)*ldo + colg) = {h0,h1};
                *reinterpret_cast<__nv_bfloat162*>(olo + (size_t)(row+8)*ldo + colg) = {l0,l1};
            }
        }
    } else { // EPI_LNRES: x_out += LN(acc + bias); xq = LN(new x_out) split
        __syncthreads();
        float* sf = reinterpret_cast<float*>(sm);        // [128][132]
#pragma unroll
        for (int mt = 0; mt < 2; mt++){
            const int lr = wm*32 + mt*16 + (lane >> 2);
#pragma unroll
            for (int nt = 0; nt < 8; nt++){
                const int lc = wn*64 + nt*8 + ((lane & 3) << 1);
                const float b0 = bias[lc], b1 = bias[lc+1];
                sf[lr*132 + lc]       = acc[mt][nt][0] + b0;
                sf[lr*132 + lc + 1]   = acc[mt][nt][1] + b1;
                sf[(lr+8)*132 + lc]   = acc[mt][nt][2] + b0;
                sf[(lr+8)*132 + lc+1] = acc[mt][nt][3] + b1;
            }
        }
        __syncthreads();
        const float4 gg = reinterpret_cast<const float4*>(lng)[lane];
        const float4 lb = reinterpret_cast<const float4*>(lnb)[lane];
        for (int r = wid*16; r < wid*16 + 16; r++){
            float4 v = *reinterpret_cast<float4*>(sf + r*132 + lane*4);
            float mu = wredsum(v.x+v.y+v.z+v.w) * (1.0f/128.0f);
            float dx=v.x-mu, dy=v.y-mu, dz=v.z-mu, dw=v.w-mu;
            float var = wredsum(dx*dx+dy*dy+dz*dz+dw*dw) * (1.0f/128.0f);
            float rs = rsqrtf(var + 1e-5f);
            const int row = mBase + r;
            float* rp = res + (size_t)row*DIM;
            float4 r4 = reinterpret_cast<float4*>(rp)[lane];
            float o[4];
            o[0] = r4.x + dx*rs*gg.x + lb.x;
            o[1] = r4.y + dy*rs*gg.y + lb.y;
            o[2] = r4.z + dz*rs*gg.z + lb.z;
            o[3] = r4.w + dw*rs*gg.w + lb.w;
            float4 o4 = make_float4(o[0],o[1],o[2],o[3]);
            reinterpret_cast<float4*>(rp)[lane] = o4;
            if (writeFinal)
                reinterpret_cast<float4*>(fin + (size_t)row*DIM)[lane] = o4;
            float mu2 = wredsum(o[0]+o[1]+o[2]+o[3]) * (1.0f/128.0f);
            float e0=o[0]-mu2, e1=o[1]-mu2, e2=o[2]-mu2, e3=o[3]-mu2;
            float var2 = wredsum(e0*e0+e1*e1+e2*e2+e3*e3) * (1.0f/128.0f);
            float rs2 = rsqrtf(var2 + 1e-5f);
            float x2[4];
            x2[0] = e0*rs2*gg.x + lb.x; x2[1] = e1*rs2*gg.y + lb.y;
            x2[2] = e2*rs2*gg.z + lb.z; x2[3] = e3*rs2*gg.w + lb.w;
            split_store4(ohi + (size_t)row*DIM + lane*4,
                         olo + (size_t)row*DIM + lane*4, x2);
        }
    }
}

// ---------------- conv weight transpose: [o][i][kh][kw] -> [tap][i][o] -------
__global__ void transpose_cw_kernel(const float* __restrict__ cw){
    int idx = blockIdx.x * blockDim.x + threadIdx.x;
    if (idx >= 9*DIM*DIM) return;
    int o   = idx / (DIM*9);
    int rem = idx - o*(DIM*9);
    int i   = rem / 9;
    int tap = rem - i*9;
    g_cwT[(size_t)tap*DIM*DIM + i*DIM + o] = cw[idx];
}

// ---------------- weight transpose + split: in[K,N] -> out[N,K] hi/lo --------
__global__ void tsplit_kernel(const float* __restrict__ in,
                              __nv_bfloat16* __restrict__ oh,
                              __nv_bfloat16* __restrict__ ol,
                              int K, int N)
{
    int idx = blockIdx.x*256 + threadIdx.x;
    if (idx >= K*N) return;
    int k = idx / N, n = idx - k*N;
    __nv_bfloat16 h, l;
    split2(in[idx], h, l);
    oh[(size_t)n*K + k] = h;
    ol[(size_t)n*K + k] = l;
}

// ---------------- row split (optional LN): fp32 -> bf16 hi/lo ----------------
template<bool DO_LN>
__global__ void __launch_bounds__(256) split_kernel(
    const float* __restrict__ in,
    __nv_bfloat16* __restrict__ oh, __nv_bfloat16* __restrict__ ol,
    const float* __restrict__ g, const float* __restrict__ b)
{
    const int lane = threadIdx.x & 31, warp = threadIdx.x >> 5;
    const size_t row = (size_t)blockIdx.x*8 + warp;
    float4 v = reinterpret_cast<const float4*>(in + row*DIM)[lane];
    if (DO_LN){
        float mu = wredsum(v.x+v.y+v.z+v.w) * (1.0f/DIM);
        float dx=v.x-mu, dy=v.y-mu, dz=v.z-mu, dw=v.w-mu;
        float var = wredsum(dx*dx+dy*dy+dz*dz+dw*dw) * (1.0f/DIM);
        float rs = rsqrtf(var + 1e-5f);
        float4 gg = reinterpret_cast<const float4*>(g)[lane];
        float4 bb = reinterpret_cast<const float4*>(b)[lane];
        v.x = dx*rs*gg.x + bb.x; v.y = dy*rs*gg.y + bb.y;
        v.z = dz*rs*gg.z + bb.z; v.w = dw*rs*gg.w + bb.w;
    }
    float t[4] = {v.x, v.y, v.z, v.w};
    split_store4(oh + row*DIM + lane*4, ol + row*DIM + lane*4, t);
}

// ---------------- conv (FFMA) + dual-LN epilogue with bf16 split -------------
__global__ void __launch_bounds__(256) conv_kernel(
    const float* __restrict__ X,
    const float* __restrict__ lng, const float* __restrict__ lnb)
{
    __shared__ __align__(16) float As[32*68];
    __shared__ __align__(16) float Bs[32*128];
    const int tid = threadIdx.x;
    const int tx = tid & 15, ty = tid >> 4;
    const int base = blockIdx.x * 64;
    const int b = base >> 12;

    float acc[4][8];
#pragma unroll
    for (int r = 0; r < 4; r++)
#pragma unroll
        for (int c = 0; c < 8; c++) acc[r][c] = 0.f;

    for (int ch = 0; ch < 36; ch++){
        const int tap = ch >> 2;
        const int k0  = (ch & 3) * 32;
        const int kh = tap/3 - 1, kw = tap%3 - 1;
#pragma unroll
        for (int i = 0; i < 2; i++){
            int idx = tid + i*256;
            int m = idx & 63, q = idx >> 6;
            int hw = (base + m) & 4095;
            int h = hw >> 6, w = hw & 63;
            int hi = 2*h + kh, wi = 2*w + kw;
            float4 a = make_float4(0.f,0.f,0.f,0.f);
            if ((unsigned)hi < HI && (unsigned)wi < WI)
                a = *reinterpret_cast<const float4*>(
                      X + ((size_t)b*NPIX_IN + hi*WI + wi)*DIM + k0 + q*4);
            As[(q*4+0)*68 + m] = a.x;
            As[(q*4+1)*68 + m] = a.y;
            As[(q*4+2)*68 + m] = a.z;
            As[(q*4+3)*68 + m] = a.w;
        }
#pragma unroll
        for (int i = 0; i < 4; i++){
            int idx = tid + i*256;
            int c4 = idx & 31, kk = idx >> 5;
            *reinterpret_cast<float4*>(Bs + kk*128 + c4*4) =
                *reinterpret_cast<const float4*>(g_cwT + (size_t)tap*DIM*DIM + (k0+kk)*128 + c4*4);
        }
        __syncthreads();
#pragma unroll 8
        for (int k = 0; k < 32; k++){
            float4 a0 = *reinterpret_cast<float4*>(As + k*68 + ty*4);
            float4 b0 = *reinterpret_cast<float4*>(Bs + k*128 + tx*8);
            float4 b1 = *reinterpret_cast<float4*>(Bs + k*128 + tx*8 + 4);
            float av[4] = {a0.x,a0.y,a0.z,a0.w};
            float bv[8] = {b0.x,b0.y,b0.z,b0.w,b1.x,b1.y,b1.z,b1.w};
#pragma unroll
            for (int r = 0; r < 4; r++)
#pragma unroll
                for (int c = 0; c < 8; c++)
                    acc[r][c] += av[r]*bv[c];
        }
        __syncthreads();
    }

    const int row0 = base + ty*4;
    const int c0 = tx*8;
    float gg[8], be[8];
#pragma unroll
    for (int c = 0; c < 8; c++){ gg[c] = lng[c0+c]; be[c] = lnb[c0+c]; }
#pragma unroll
    for (int r = 0; r < 4; r++){
        float v[8]; float s = 0.f;
#pragma unroll
        for (int c = 0; c < 8; c++){ v[c] = acc[r][c]; s += v[c]; }
        float mu = redsum16(s) * (1.0f/128.0f);
        float s2 = 0.f;
#pragma unroll
        for (int c = 0; c < 8; c++){ v[c] -= mu; s2 += v[c]*v[c]; }
        float rs = rsqrtf(redsum16(s2)*(1.0f/128.0f) + 1e-5f);
        float o[8];
#pragma unroll
        for (int c = 0; c < 8; c++) o[c] = v[c]*rs*gg[c] + be[c];
        float* op = g_xout + (size_t)(row0+r)*DIM + c0;
        reinterpret_cast<float4*>(op)[0] = make_float4(o[0],o[1],o[2],o[3]);
        reinterpret_cast<float4*>(op)[1] = make_float4(o[4],o[5],o[6],o[7]);
        float t = 0.f;
#pragma unroll
        for (int c = 0; c < 8; c++) t += o[c];
        float mu2 = redsum16(t) * (1.0f/128.0f);
        float t2 = 0.f;
#pragma unroll
        for (int c = 0; c < 8; c++){ o[c] -= mu2; t2 += o[c]*o[c]; }
        float rs2 = rsqrtf(redsum16(t2)*(1.0f/128.0f) + 1e-5f);
        float x2[8];
#pragma unroll
        for (int c = 0; c < 8; c++) x2[c] = o[c]*rs2*gg[c] + be[c];
        split_store8(g_xq_h + (size_t)(row0+r)*DIM + c0,
                     g_xq_l + (size_t)(row0+r)*DIM + c0, x2);
    }
}

// ---------------- zero column sums -------------------------------------------
__global__ void zero_colsum_kernel(){
    g_colsum[blockIdx.x*blockDim.x + threadIdx.x] = 0.f;
}

// ---------------- attention: scores + softmax + eps + colsum atomics ---------
__global__ void attn_kernel(const float* __restrict__ rpb,
                            const float* __restrict__ tau,
                            float* __restrict__ attn_out)
{
    const int tid = threadIdx.x, warp = tid >> 5, lane = tid & 31;
    const int id  = blockIdx.x*4 + warp;
    const int b   = id >> 14;
    const int rem = id & 16383;
    const int g   = rem >> 12;
    const int hw  = rem & 4095;
    const int h = hw >> 6, w = hw & 63;
    const int ga = g >> 1, gb = g & 1;
    const int pix = (2*h + ga)*WI + 2*w + gb;
    const float4 kv = reinterpret_cast<const float4*>(g_k + ((size_t)b*NPIX_IN + pix)*DIM)[lane];
    const float scale = expf(tau[0]);
    const int ch = min(max(h,1), HO-2), cw = min(max(w,1), WO-2);

    float p[9];
    float m = -1e30f;
#pragma unroll
    for (int t = 0; t < 9; t++){
        const int nh = ch + t/3 - 1, nw = cw + t%3 - 1;
        const float4 q4 = reinterpret_cast<const float4*>(g_q + ((size_t)b*NPIX_OUT + nh*WO + nw)*DIM)[lane];
        float d = kv.x*q4.x + kv.y*q4.y + kv.z*q4.z + kv.w*q4.w;
        d = wredsum(d);
        const float val = (d + rpb[g*9 + t]) * scale;
        p[t] = val;
        m = fmaxf(m, val);
    }
    float s = 0.f;
#pragma unroll
    for (int t = 0; t < 9; t++){ p[t] = expf(p[t] - m); s += p[t]; }
    const float inv = 1.f/s;
#pragma unroll
    for (int t = 0; t < 9; t++) p[t] = p[t]*inv + 1e-6f;

    if (lane == 0){
        float* ao = attn_out + (size_t)id*9;
#pragma unroll
        for (int t = 0; t < 9; t++) ao[t] = p[t];
#pragma unroll
        for (int t = 0; t < 9; t++){
            const int nh = ch + t/3 - 1, nw = cw + t%3 - 1;
            atomicAdd(&g_colsum[b*NPIX_OUT + nh*WO + nw], p[t]);
        }
    }
}

// ---------------- aggregation: A_col + upd + residual + xout split -----------
__global__ void upd_kernel(const float* __restrict__ attn_in,
                           float* __restrict__ acol_out)
{
    const int tid = threadIdx.x, warp = tid >> 5, lane = tid & 31;
    const int id = blockIdx.x*4 + warp;
    const int b  = id >> 12;
    const int hw = id & 4095;
    const int h = hw >> 6, w = hw & 63;
    const int ch = min(max(h,1), HO-2), cw = min(max(w,1), WO-2);

    float inv_dn[9];
#pragma unroll
    for (int t = 0; t < 9; t++){
        const int nh = ch + t/3 - 1, nw = cw + t%3 - 1;
        inv_dn[t] = 1.0f / (g_colsum[b*NPIX_OUT + nh*WO + nw] + 1e-8f);
    }
    float4 acc = make_float4(0.f,0.f,0.f,0.f);
#pragma unroll
    for (int g = 0; g < 4; g++){
        const int ga = g >> 1, gb = g & 1;
        const size_t base = ((size_t)((b*4 + g)*NPIX_OUT) + hw)*9;
        const float* ab = attn_in + base;
        float* cb = acol_out + base;
#pragma unroll
        for (int t = 0; t < 9; t++){
            const float coeff = ab[t] * inv_dn[t];
            if (lane == 0) cb[t] = coeff;
            const int nh = ch + t/3 - 1, nw = cw + t%3 - 1;
            const int pix = (2*nh + ga)*WI + 2*nw + gb;
            const float4 vv = reinterpret_cast<const float4*>(g_v + ((size_t)b*NPIX_IN + pix)*DIM)[lane];
            acc.x += coeff*vv.x; acc.y += coeff*vv.y; acc.z += coeff*vv.z; acc.w += coeff*vv.w;
        }
    }
    float4* xo = reinterpret_cast<float4*>(g_xout + (size_t)id*DIM);
    float4 v = xo[lane];
    v.x += acc.x; v.y += acc.y; v.z += acc.z; v.w += acc.w;
    xo[lane] = v;
    float t4[4] = {v.x, v.y, v.z, v.w};
    split_store4(g_xo_h + (size_t)id*DIM + lane*4,
                 g_xo_l + (size_t)id*DIM + lane*4, t4);
}

// ---------------- launch ------------------------------------------------------
extern "C" void kernel_launch(void* const* d_in, const int* in_sizes, int n_in,
                              void* d_out, int out_size)
{
    const float* x      = (const float*)d_in[0];
    const float* convw  = (const float*)d_in[1];
    const float* q_w    = (const float*)d_in[2];
    const float* k_w    = (const float*)d_in[3];
    const float* v_w    = (const float*)d_in[4];
    const float* w1     = (const float*)d_in[5];
    const float* b1     = (const float*)d_in[6];
    const float* w2     = (const float*)d_in[7];
    const float* b2     = (const float*)d_in[8];
    const float* lin_g  = (const float*)d_in[9];
    const float* lin_b  = (const float*)d_in[10];
    const float* lout_g = (const float*)d_in[11];
    const float* lout_b = (const float*)d_in[12];
    const float* tau    = (const float*)d_in[13];
    const float* rpb    = (const float*)d_in[14];

    float* out      = (float*)d_out;
    float* out_x    = out;
    float* out_attn = out + (size_t)NROWS_OUT*DIM;
    float* out_acol = out_attn + (size_t)BATCH*4*NPIX_OUT*9;

    float *pk, *pv, *pq, *pxout;
    cudaGetSymbolAddress((void**)&pk,    g_k);
    cudaGetSymbolAddress((void**)&pv,    g_v);
    cudaGetSymbolAddress((void**)&pq,    g_q);
    cudaGetSymbolAddress((void**)&pxout, g_xout);
    __nv_bfloat16 *pxh,*pxl,*plih,*plil,*poh,*pol,*pqh,*pql,*phh,*phl;
    __nv_bfloat16 *wqh,*wql,*wkh,*wkl,*wvh,*wvl,*w1h,*w1l,*w2h,*w2l;
    cudaGetSymbolAddress((void**)&pxh,  g_x_h);   cudaGetSymbolAddress((void**)&pxl,  g_x_l);
    cudaGetSymbolAddress((void**)&plih, g_xli_h); cudaGetSymbolAddress((void**)&plil, g_xli_l);
    cudaGetSymbolAddress((void**)&poh,  g_xo_h);  cudaGetSymbolAddress((void**)&pol,  g_xo_l);
    cudaGetSymbolAddress((void**)&pqh,  g_xq_h);  cudaGetSymbolAddress((void**)&pql,  g_xq_l);
    cudaGetSymbolAddress((void**)&phh,  g_hh_h);  cudaGetSymbolAddress((void**)&phl,  g_hh_l);
    cudaGetSymbolAddress((void**)&wqh,  g_wq_h);  cudaGetSymbolAddress((void**)&wql,  g_wq_l);
    cudaGetSymbolAddress((void**)&wkh,  g_wk_h);  cudaGetSymbolAddress((void**)&wkl,  g_wk_l);
    cudaGetSymbolAddress((void**)&wvh,  g_wv_h);  cudaGetSymbolAddress((void**)&wvl,  g_wv_l);
    cudaGetSymbolAddress((void**)&w1h,  g_w1_h);  cudaGetSymbolAddress((void**)&w1l,  g_w1_l);
    cudaGetSymbolAddress((void**)&w2h,  g_w2_h);  cudaGetSymbolAddress((void**)&w2l,  g_w2_l);

    cudaFuncSetAttribute(gemm_mma, cudaFuncAttributeMaxDynamicSharedMemorySize, SMEM_MMA);

    // ---- preprocessing ----
    transpose_cw_kernel<<<(9*DIM*DIM + 255)/256, 256>>>(convw);
    tsplit_kernel<<<(DIM*DIM)/256, 256>>>(q_w, wqh, wql, DIM, DIM);
    tsplit_kernel<<<(DIM*DIM)/256, 256>>>(k_w, wkh, wkl, DIM, DIM);
    tsplit_kernel<<<(DIM*DIM)/256, 256>>>(v_w, wvh, wvl, DIM, DIM);
    tsplit_kernel<<<(2*DIM*DIM)/256, 256>>>(w1, w1h, w1l, DIM, 2*DIM);   // -> [256,128]
    tsplit_kernel<<<(2*DIM*DIM)/256, 256>>>(w2, w2h, w2l, 2*DIM, DIM);   // -> [128,256]
    split_kernel<false><<<NROWS_IN/8, 256>>>(x, pxh, pxl, nullptr, nullptr);
    split_kernel<true ><<<NROWS_IN/8, 256>>>(x, plih, plil, lin_g, lin_b);

    // k = LN_in(x) @ k_w ; v = x @ v_w
    gemm_mma<<<NROWS_IN/128, 256, SMEM_MMA>>>(plih, plil, 128, wkh, wkl,
        nullptr, nullptr, nullptr, pk, 128, nullptr, nullptr, nullptr, nullptr, 0,
        EPI_STORE, 0);
    gemm_mma<<<NROWS_IN/128, 256, SMEM_MMA>>>(pxh, pxl, 128, wvh, wvl,
        nullptr, nullptr, nullptr, pv, 128, nullptr, nullptr, nullptr, nullptr, 0,
        EPI_STORE, 0);
    conv_kernel<<<NROWS_OUT/64, 256>>>(x, lout_g, lout_b);

    for (int it = 0; it < 3; it++){
        zero_colsum_kernel<<<(BATCH*NPIX_OUT)/256, 256>>>();
        // q = LN(x_out) @ q_w
        gemm_mma<<<NROWS_OUT/128, 256, SMEM_MMA>>>(pqh, pql, 128, wqh, wql,
            nullptr, nullptr, nullptr, pq, 128, nullptr, nullptr, nullptr, nullptr, 0,
            EPI_STORE, 0);
        attn_kernel<<<(BATCH*4*NPIX_OUT)/4, 128>>>(rpb, tau, out_attn);
        upd_kernel<<<NROWS_OUT/4, 128>>>(out_attn, out_acol);
        // h = gelu(x_out @ w1 + b1) -> bf16 split
        gemm_mma<<<dim3(NROWS_OUT/128, 2), 256, SMEM_MMA>>>(poh, pol, 128, w1h, w1l,
            b1, nullptr, nullptr, nullptr, 0, nullptr, nullptr, phh, phl, 256,
            EPI_GELU, 0);
        // x_out += LN(h @ w2 + b2); xq = LN(x_out) split
        gemm_mma<<<NROWS_OUT/128, 256, SMEM_MMA>>>(phh, phl, 256, w2h, w2l,
            b2, lout_g, lout_b, nullptr, 0, pxout, out_x, pqh, pql, 128,
            EPI_LNRES, it == 2 ? 1 : 0);
    }
    (void)in_sizes; (void)n_in; (void)out_size;
}

// round 11
// speedup vs baseline: 1.7183x; 1.2647x over previous
#include <cuda_runtime.h>
#include <cuda_bf16.h>
#include <math.h>
#include <stdint.h>

#define BATCH 4
#define HI 128
#define WI 128
#define HO 64
#define WO 64
#define DIM 128
#define NPIX_IN  (HI*WI)
#define NPIX_OUT (HO*WO)
#define NROWS_IN  (BATCH*NPIX_IN)   // 65536
#define NROWS_OUT (BATCH*NPIX_OUT)  // 16384

// ---------------- scratch (device globals) ----------------------------------
__device__ float g_k   [(size_t)NROWS_IN*DIM];
__device__ float g_v   [(size_t)NROWS_IN*DIM];
__device__ float g_q   [(size_t)NROWS_OUT*DIM];
__device__ float g_xout[(size_t)NROWS_OUT*DIM];
__device__ float g_colsum[BATCH*NPIX_OUT];

// bf16 split buffers (hi/lo)
__device__ __align__(16) __nv_bfloat16 g_x_h  [(size_t)NROWS_IN*DIM];
__device__ __align__(16) __nv_bfloat16 g_x_l  [(size_t)NROWS_IN*DIM];
__device__ __align__(16) __nv_bfloat16 g_xli_h[(size_t)NROWS_IN*DIM];   // LN_in(x)
__device__ __align__(16) __nv_bfloat16 g_xli_l[(size_t)NROWS_IN*DIM];
__device__ __align__(16) __nv_bfloat16 g_xo_h [(size_t)NROWS_OUT*DIM];  // xout (post-upd)
__device__ __align__(16) __nv_bfloat16 g_xo_l [(size_t)NROWS_OUT*DIM];
__device__ __align__(16) __nv_bfloat16 g_xq_h [(size_t)NROWS_OUT*DIM];  // LN(xout)
__device__ __align__(16) __nv_bfloat16 g_xq_l [(size_t)NROWS_OUT*DIM];
__device__ __align__(16) __nv_bfloat16 g_hh_h [(size_t)NROWS_OUT*2*DIM];
__device__ __align__(16) __nv_bfloat16 g_hh_l [(size_t)NROWS_OUT*2*DIM];
// transposed-split weights [N,K]
__device__ __align__(16) __nv_bfloat16 g_wq_h[DIM*DIM], g_wq_l[DIM*DIM];
__device__ __align__(16) __nv_bfloat16 g_wk_h[DIM*DIM], g_wk_l[DIM*DIM];
__device__ __align__(16) __nv_bfloat16 g_wv_h[DIM*DIM], g_wv_l[DIM*DIM];
__device__ __align__(16) __nv_bfloat16 g_w1_h[2*DIM*DIM], g_w1_l[2*DIM*DIM]; // [256,128]
__device__ __align__(16) __nv_bfloat16 g_w2_h[2*DIM*DIM], g_w2_l[2*DIM*DIM]; // [128,256]
// conv weights per tap: [tap][o][i] bf16 split
__device__ __align__(16) __nv_bfloat16 g_cw_h[9*DIM*DIM], g_cw_l[9*DIM*DIM];

// ---------------- helpers ----------------------------------------------------
static __device__ __forceinline__ float wredsum(float v){
#pragma unroll
    for (int o = 16; o > 0; o >>= 1) v += __shfl_xor_sync(0xffffffffu, v, o);
    return v;
}
static __device__ __forceinline__ float geluf(float x){
    return 0.5f * x * (1.0f + erff(x * 0.70710678118654752440f));
}
static __device__ __forceinline__ uint32_t smem_u32(const void* p){
    uint32_t a;
    asm("{ .reg .u64 t; cvta.to.shared.u64 t, %1; cvt.u32.u64 %0, t; }" : "=r"(a) : "l"(p));
    return a;
}
static __device__ __forceinline__ void split2(float v, __nv_bfloat16& h, __nv_bfloat16& l){
    h = __float2bfloat16(v);
    l = __float2bfloat16(v - __bfloat162float(h));
}
static __device__ __forceinline__ void split_store4(
    __nv_bfloat16* ph, __nv_bfloat16* pl, const float* v)
{
    __nv_bfloat16 h[4], l[4];
#pragma unroll
    for (int i = 0; i < 4; i++) split2(v[i], h[i], l[i]);
    *reinterpret_cast<uint2*>(ph) = *reinterpret_cast<const uint2*>(h);
    *reinterpret_cast<uint2*>(pl) = *reinterpret_cast<const uint2*>(l);
}

// ---------------- mma primitives (baseline PTX: sm_80-compatible) -----------
static __device__ __forceinline__ void ldsm_x4(uint32_t* r, uint32_t addr){
    asm volatile("ldmatrix.sync.aligned.m8n8.x4.shared.b16 {%0,%1,%2,%3}, [%4];"
        : "=r"(r[0]), "=r"(r[1]), "=r"(r[2]), "=r"(r[3]) : "r"(addr));
}
static __device__ __forceinline__ void mma16816(
    float* c, const uint32_t* a, uint32_t b0, uint32_t b1)
{
    asm volatile(
        "mma.sync.aligned.m16n8k16.row.col.f32.bf16.bf16.f32 "
        "{%0,%1,%2,%3}, {%4,%5,%6,%7}, {%8,%9}, {%0,%1,%2,%3};"
        : "+f"(c[0]), "+f"(c[1]), "+f"(c[2]), "+f"(c[3])
        : "r"(a[0]), "r"(a[1]), "r"(a[2]), "r"(a[3]), "r"(b0), "r"(b1));
}

#define EPI_STORE 0
#define EPI_GELU  1
#define EPI_LNRES 2

#define TSTRIDE 72                      // bf16 elements per smem row (pad 64->72)
#define TBYTES  (128*TSTRIDE*2)         // 18432 bytes per tile
#define OFF_AH  0
#define OFF_AL  (TBYTES)
#define OFF_BH  (2*TBYTES)
#define OFF_BL  (3*TBYTES)
#define SMEM_MMA (4*TBYTES)             // 73728

// ---------------- bf16-3x tensor-core GEMM -----------------------------------
// D[128 tile, 128 tile] = A @ B^T; A[M,Ktot] hi/lo, B[N,Ktot] hi/lo (row-major).
__global__ void __launch_bounds__(256) gemm_mma(
    const __nv_bfloat16* __restrict__ Ah, const __nv_bfloat16* __restrict__ Al, int Ktot,
    const __nv_bfloat16* __restrict__ Bh, const __nv_bfloat16* __restrict__ Bl,
    const float* __restrict__ bias,
    const float* __restrict__ lng, const float* __restrict__ lnb,
    float* __restrict__ C, int ldc,
    float* __restrict__ res, float* __restrict__ fin,
    __nv_bfloat16* __restrict__ ohi, __nv_bfloat16* __restrict__ olo, int ldo,
    int epi, int writeFinal)
{
    extern __shared__ char sm[];
    const uint32_t smb = smem_u32(sm);
    const int tid = threadIdx.x, wid = tid >> 5, lane = tid & 31;
    const int wm = wid & 3, wn = wid >> 2;
    const int mBase = blockIdx.x * 128;
    const int col0  = blockIdx.y * 128;

    float acc[2][8][4];
#pragma unroll
    for (int mt = 0; mt < 2; mt++)
#pragma unroll
        for (int nt = 0; nt < 8; nt++)
#pragma unroll
            for (int i = 0; i < 4; i++) acc[mt][nt][i] = 0.f;

    const __nv_bfloat16* Ah0 = Ah + (size_t)mBase*Ktot;
    const __nv_bfloat16* Al0 = Al + (size_t)mBase*Ktot;
    const __nv_bfloat16* Bh0 = Bh + (size_t)col0*Ktot;
    const __nv_bfloat16* Bl0 = Bl + (size_t)col0*Ktot;

    const int aRow = lane & 15, aKh = (lane >> 4) << 3;
    const int bRow = (lane & 7) + ((lane >> 4) << 3);
    const int bKh  = ((lane >> 3) & 1) << 3;

    for (int kc = 0; kc < Ktot; kc += 64){
        __syncthreads();
#pragma unroll
        for (int i = 0; i < 4; i++){
            int u = tid + i*256;
            int m = u >> 3, c8 = (u & 7) << 3;
            size_t go = (size_t)m*Ktot + kc + c8;
            int so = (m*TSTRIDE + c8) << 1;
            *reinterpret_cast<uint4*>(sm + OFF_AH + so) = *reinterpret_cast<const uint4*>(Ah0 + go);
            *reinterpret_cast<uint4*>(sm + OFF_AL + so) = *reinterpret_cast<const uint4*>(Al0 + go);
            *reinterpret_cast<uint4*>(sm + OFF_BH + so) = *reinterpret_cast<const uint4*>(Bh0 + go);
            *reinterpret_cast<uint4*>(sm + OFF_BL + so) = *reinterpret_cast<const uint4*>(Bl0 + go);
        }
        __syncthreads();

#pragma unroll
        for (int ks = 0; ks < 4; ks++){
            uint32_t ah[2][4], al[2][4];
#pragma unroll
            for (int mt = 0; mt < 2; mt++){
                const int eoff = ((wm*32 + mt*16 + aRow)*TSTRIDE + ks*16 + aKh) << 1;
                ldsm_x4(ah[mt], smb + OFF_AH + eoff);
                ldsm_x4(al[mt], smb + OFF_AL + eoff);
            }
#pragma unroll
            for (int np = 0; np < 4; np++){
                const int eoff = ((wn*64 + np*16 + bRow)*TSTRIDE + ks*16 + bKh) << 1;
                uint32_t bh4[4], bl4[4];
                ldsm_x4(bh4, smb + OFF_BH + eoff);
                ldsm_x4(bl4, smb + OFF_BL + eoff);
#pragma unroll
                for (int mt = 0; mt < 2; mt++){
#pragma unroll
                    for (int hf = 0; hf < 2; hf++){
                        float* c = acc[mt][np*2 + hf];
                        mma16816(c, ah[mt], bh4[hf*2], bh4[hf*2+1]);
                        mma16816(c, al[mt], bh4[hf*2], bh4[hf*2+1]);
                        mma16816(c, ah[mt], bl4[hf*2], bl4[hf*2+1]);
                    }
                }
            }
        }
    }

    // ---------------- epilogues ----------------
    if (epi == EPI_STORE){
#pragma unroll
        for (int mt = 0; mt < 2; mt++){
            const int row = mBase + wm*32 + mt*16 + (lane >> 2);
#pragma unroll
            for (int nt = 0; nt < 8; nt++){
                const int colg = col0 + wn*64 + nt*8 + ((lane & 3) << 1);
                *reinterpret_cast<float2*>(C + (size_t)row*ldc + colg) =
                    make_float2(acc[mt][nt][0], acc[mt][nt][1]);
                *reinterpret_cast<float2*>(C + (size_t)(row+8)*ldc + colg) =
                    make_float2(acc[mt][nt][2], acc[mt][nt][3]);
            }
        }
    } else if (epi == EPI_GELU){
#pragma unroll
        for (int mt = 0; mt < 2; mt++){
            const int row = mBase + wm*32 + mt*16 + (lane >> 2);
#pragma unroll
            for (int nt = 0; nt < 8; nt++){
                const int colg = col0 + wn*64 + nt*8 + ((lane & 3) << 1);
                const float b0 = bias[colg], b1 = bias[colg+1];
                float v0 = geluf(acc[mt][nt][0] + b0);
                float v1 = geluf(acc[mt][nt][1] + b1);
                float v2 = geluf(acc[mt][nt][2] + b0);
                float v3 = geluf(acc[mt][nt][3] + b1);
                __nv_bfloat16 h0,l0,h1,l1;
                split2(v0,h0,l0); split2(v1,h1,l1);
                *reinterpret_cast<__nv_bfloat162*>(ohi + (size_t)row*ldo + colg) = {h0,h1};
                *reinterpret_cast<__nv_bfloat162*>(olo + (size_t)row*ldo + colg) = {l0,l1};
                split2(v2,h0,l0); split2(v3,h1,l1);
                *reinterpret_cast<__nv_bfloat162*>(ohi + (size_t)(row+8)*ldo + colg) = {h0,h1};
                *reinterpret_cast<__nv_bfloat162*>(olo + (size_t)(row+8)*ldo + colg) = {l0,l1};
            }
        }
    } else { // EPI_LNRES
        __syncthreads();
        float* sf = reinterpret_cast<float*>(sm);
#pragma unroll
        for (int mt = 0; mt < 2; mt++){
            const int lr = wm*32 + mt*16 + (lane >> 2);
#pragma unroll
            for (int nt = 0; nt < 8; nt++){
                const int lc = wn*64 + nt*8 + ((lane & 3) << 1);
                const float b0 = bias[lc], b1 = bias[lc+1];
                sf[lr*132 + lc]       = acc[mt][nt][0] + b0;
                sf[lr*132 + lc + 1]   = acc[mt][nt][1] + b1;
                sf[(lr+8)*132 + lc]   = acc[mt][nt][2] + b0;
                sf[(lr+8)*132 + lc+1] = acc[mt][nt][3] + b1;
            }
        }
        __syncthreads();
        const float4 gg = reinterpret_cast<const float4*>(lng)[lane];
        const float4 lb = reinterpret_cast<const float4*>(lnb)[lane];
        for (int r = wid*16; r < wid*16 + 16; r++){
            float4 v = *reinterpret_cast<float4*>(sf + r*132 + lane*4);
            float mu = wredsum(v.x+v.y+v.z+v.w) * (1.0f/128.0f);
            float dx=v.x-mu, dy=v.y-mu, dz=v.z-mu, dw=v.w-mu;
            float var = wredsum(dx*dx+dy*dy+dz*dz+dw*dw) * (1.0f/128.0f);
            float rs = rsqrtf(var + 1e-5f);
            const int row = mBase + r;
            float* rp = res + (size_t)row*DIM;
            float4 r4 = reinterpret_cast<float4*>(rp)[lane];
            float o[4];
            o[0] = r4.x + dx*rs*gg.x + lb.x;
            o[1] = r4.y + dy*rs*gg.y + lb.y;
            o[2] = r4.z + dz*rs*gg.z + lb.z;
            o[3] = r4.w + dw*rs*gg.w + lb.w;
            float4 o4 = make_float4(o[0],o[1],o[2],o[3]);
            reinterpret_cast<float4*>(rp)[lane] = o4;
            if (writeFinal)
                reinterpret_cast<float4*>(fin + (size_t)row*DIM)[lane] = o4;
            float mu2 = wredsum(o[0]+o[1]+o[2]+o[3]) * (1.0f/128.0f);
            float e0=o[0]-mu2, e1=o[1]-mu2, e2=o[2]-mu2, e3=o[3]-mu2;
            float var2 = wredsum(e0*e0+e1*e1+e2*e2+e3*e3) * (1.0f/128.0f);
            float rs2 = rsqrtf(var2 + 1e-5f);
            float x2[4];
            x2[0] = e0*rs2*gg.x + lb.x; x2[1] = e1*rs2*gg.y + lb.y;
            x2[2] = e2*rs2*gg.z + lb.z; x2[3] = e3*rs2*gg.w + lb.w;
            split_store4(ohi + (size_t)row*DIM + lane*4,
                         olo + (size_t)row*DIM + lane*4, x2);
        }
    }
}

// ---------------- conv as implicit tensor-core GEMM --------------------------
// 128 out-pixels x 128 out-channels per block; K = 9 taps x 128, gathered A.
__global__ void __launch_bounds__(256) conv_mma(
    const float* __restrict__ lng, const float* __restrict__ lnb)
{
    extern __shared__ char sm[];
    const uint32_t smb = smem_u32(sm);
    const int tid = threadIdx.x, wid = tid >> 5, lane = tid & 31;
    const int wm = wid & 3, wn = wid >> 2;
    const int mBase = blockIdx.x * 128;

    float acc[2][8][4];
#pragma unroll
    for (int mt = 0; mt < 2; mt++)
#pragma unroll
        for (int nt = 0; nt < 8; nt++)
#pragma unroll
            for (int i = 0; i < 4; i++) acc[mt][nt][i] = 0.f;

    const int aRow = lane & 15, aKh = (lane >> 4) << 3;
    const int bRow = (lane & 7) + ((lane >> 4) << 3);
    const int bKh  = ((lane >> 3) & 1) << 3;

    for (int tap = 0; tap < 9; tap++){
        const int kh = tap/3 - 1, kw = tap%3 - 1;
        for (int kc = 0; kc < 2; kc++){
            __syncthreads();
#pragma unroll
            for (int i = 0; i < 4; i++){
                int u = tid + i*256;
                int m = u >> 3, c8 = (u & 7) << 3;
                const int p = mBase + m;
                const int b = p >> 12, hw = p & 4095;
                const int h = hw >> 6, w = hw & 63;
                const int hi = 2*h + kh, wi = 2*w + kw;
                uint4 vh = make_uint4(0,0,0,0), vl = make_uint4(0,0,0,0);
                if ((unsigned)hi < HI && (unsigned)wi < WI){
                    size_t go = ((size_t)b*NPIX_IN + hi*WI + wi)*DIM + kc*64 + c8;
                    vh = *reinterpret_cast<const uint4*>(g_x_h + go);
                    vl = *reinterpret_cast<const uint4*>(g_x_l + go);
                }
                int so = (m*TSTRIDE + c8) << 1;
                *reinterpret_cast<uint4*>(sm + OFF_AH + so) = vh;
                *reinterpret_cast<uint4*>(sm + OFF_AL + so) = vl;
                size_t gb = (size_t)tap*DIM*DIM + (size_t)m*DIM + kc*64 + c8;
                *reinterpret_cast<uint4*>(sm + OFF_BH + so) =
                    *reinterpret_cast<const uint4*>(g_cw_h + gb);
                *reinterpret_cast<uint4*>(sm + OFF_BL + so) =
                    *reinterpret_cast<const uint4*>(g_cw_l + gb);
            }
            __syncthreads();
#pragma unroll
            for (int ks = 0; ks < 4; ks++){
                uint32_t ah[2][4], al[2][4];
#pragma unroll
                for (int mt = 0; mt < 2; mt++){
                    const int eoff = ((wm*32 + mt*16 + aRow)*TSTRIDE + ks*16 + aKh) << 1;
                    ldsm_x4(ah[mt], smb + OFF_AH + eoff);
                    ldsm_x4(al[mt], smb + OFF_AL + eoff);
                }
#pragma unroll
                for (int np = 0; np < 4; np++){
                    const int eoff = ((wn*64 + np*16 + bRow)*TSTRIDE + ks*16 + bKh) << 1;
                    uint32_t bh4[4], bl4[4];
                    ldsm_x4(bh4, smb + OFF_BH + eoff);
                    ldsm_x4(bl4, smb + OFF_BL + eoff);
#pragma unroll
                    for (int mt = 0; mt < 2; mt++){
#pragma unroll
                        for (int hf = 0; hf < 2; hf++){
                            float* c = acc[mt][np*2 + hf];
                            mma16816(c, ah[mt], bh4[hf*2], bh4[hf*2+1]);
                            mma16816(c, al[mt], bh4[hf*2], bh4[hf*2+1]);
                            mma16816(c, ah[mt], bl4[hf*2], bl4[hf*2+1]);
                        }
                    }
                }
            }
        }
    }

    // epilogue: x_out = LN(seed); xq = LN(x_out) split
    __syncthreads();
    float* sf = reinterpret_cast<float*>(sm);
#pragma unroll
    for (int mt = 0; mt < 2; mt++){
        const int lr = wm*32 + mt*16 + (lane >> 2);
#pragma unroll
        for (int nt = 0; nt < 8; nt++){
            const int lc = wn*64 + nt*8 + ((lane & 3) << 1);
            sf[lr*132 + lc]       = acc[mt][nt][0];
            sf[lr*132 + lc + 1]   = acc[mt][nt][1];
            sf[(lr+8)*132 + lc]   = acc[mt][nt][2];
            sf[(lr+8)*132 + lc+1] = acc[mt][nt][3];
        }
    }
    __syncthreads();
    const float4 gg = reinterpret_cast<const float4*>(lng)[lane];
    const float4 lb = reinterpret_cast<const float4*>(lnb)[lane];
    for (int r = wid*16; r < wid*16 + 16; r++){
        float4 v = *reinterpret_cast<float4*>(sf + r*132 + lane*4);
        float mu = wredsum(v.x+v.y+v.z+v.w) * (1.0f/128.0f);
        float dx=v.x-mu, dy=v.y-mu, dz=v.z-mu, dw=v.w-mu;
        float var = wredsum(dx*dx+dy*dy+dz*dz+dw*dw) * (1.0f/128.0f);
        float rs = rsqrtf(var + 1e-5f);
        const int row = mBase + r;
        float o[4];
        o[0] = dx*rs*gg.x + lb.x; o[1] = dy*rs*gg.y + lb.y;
        o[2] = dz*rs*gg.z + lb.z; o[3] = dw*rs*gg.w + lb.w;
        reinterpret_cast<float4*>(g_xout + (size_t)row*DIM)[lane] =
            make_float4(o[0],o[1],o[2],o[3]);
        float mu2 = wredsum(o[0]+o[1]+o[2]+o[3]) * (1.0f/128.0f);
        float e0=o[0]-mu2, e1=o[1]-mu2, e2=o[2]-mu2, e3=o[3]-mu2;
        float var2 = wredsum(e0*e0+e1*e1+e2*e2+e3*e3) * (1.0f/128.0f);
        float rs2 = rsqrtf(var2 + 1e-5f);
        float x2[4];
        x2[0] = e0*rs2*gg.x + lb.x; x2[1] = e1*rs2*gg.y + lb.y;
        x2[2] = e2*rs2*gg.z + lb.z; x2[3] = e3*rs2*gg.w + lb.w;
        split_store4(g_xq_h + (size_t)row*DIM + lane*4,
                     g_xq_l + (size_t)row*DIM + lane*4, x2);
    }
}

// ---------------- conv weight split: [o][i][tap] -> [tap][o][i] hi/lo --------
__global__ void conv_split_kernel(const float* __restrict__ cw){
    int idx = blockIdx.x*256 + threadIdx.x;
    if (idx >= 9*DIM*DIM) return;
    int o   = idx / (DIM*9);
    int rem = idx - o*(DIM*9);
    int i   = rem / 9;
    int tap = rem - i*9;
    __nv_bfloat16 h, l;
    split2(cw[idx], h, l);
    g_cw_h[(size_t)tap*DIM*DIM + o*DIM + i] = h;
    g_cw_l[(size_t)tap*DIM*DIM + o*DIM + i] = l;
}

// ---------------- weight transpose + split: in[K,N] -> out[N,K] hi/lo --------
__global__ void tsplit_kernel(const float* __restrict__ in,
                              __nv_bfloat16* __restrict__ oh,
                              __nv_bfloat16* __restrict__ ol,
                              int K, int N)
{
    int idx = blockIdx.x*256 + threadIdx.x;
    if (idx >= K*N) return;
    int k = idx / N, n = idx - k*N;
    __nv_bfloat16 h, l;
    split2(in[idx], h, l);
    oh[(size_t)n*K + k] = h;
    ol[(size_t)n*K + k] = l;
}

// ---------------- row split (optional LN): fp32 -> bf16 hi/lo ----------------
template<bool DO_LN>
__global__ void __launch_bounds__(256) split_kernel(
    const float* __restrict__ in,
    __nv_bfloat16* __restrict__ oh, __nv_bfloat16* __restrict__ ol,
    const float* __restrict__ g, const float* __restrict__ b)
{
    const int lane = threadIdx.x & 31, warp = threadIdx.x >> 5;
    const size_t row = (size_t)blockIdx.x*8 + warp;
    float4 v = reinterpret_cast<const float4*>(in + row*DIM)[lane];
    if (DO_LN){
        float mu = wredsum(v.x+v.y+v.z+v.w) * (1.0f/DIM);
        float dx=v.x-mu, dy=v.y-mu, dz=v.z-mu, dw=v.w-mu;
        float var = wredsum(dx*dx+dy*dy+dz*dz+dw*dw) * (1.0f/DIM);
        float rs = rsqrtf(var + 1e-5f);
        float4 gg = reinterpret_cast<const float4*>(g)[lane];
        float4 bb = reinterpret_cast<const float4*>(b)[lane];
        v.x = dx*rs*gg.x + bb.x; v.y = dy*rs*gg.y + bb.y;
        v.z = dz*rs*gg.z + bb.z; v.w = dw*rs*gg.w + bb.w;
    }
    float t[4] = {v.x, v.y, v.z, v.w};
    split_store4(oh + row*DIM + lane*4, ol + row*DIM + lane*4, t);
}

// ---------------- zero column sums -------------------------------------------
__global__ void zero_colsum_kernel(){
    g_colsum[blockIdx.x*blockDim.x + threadIdx.x] = 0.f;
}

// ---------------- attention: scores + softmax + eps + colsum atomics ---------
__global__ void attn_kernel(const float* __restrict__ rpb,
                            const float* __restrict__ tau,
                            float* __restrict__ attn_out)
{
    const int tid = threadIdx.x, warp = tid >> 5, lane = tid & 31;
    const int id  = blockIdx.x*4 + warp;
    const int b   = id >> 14;
    const int rem = id & 16383;
    const int g   = rem >> 12;
    const int hw  = rem & 4095;
    const int h = hw >> 6, w = hw & 63;
    const int ga = g >> 1, gb = g & 1;
    const int pix = (2*h + ga)*WI + 2*w + gb;
    const float4 kv = reinterpret_cast<const float4*>(g_k + ((size_t)b*NPIX_IN + pix)*DIM)[lane];
    const float scale = expf(tau[0]);
    const int ch = min(max(h,1), HO-2), cw = min(max(w,1), WO-2);

    float p[9];
    float m = -1e30f;
#pragma unroll
    for (int t = 0; t < 9; t++){
        const int nh = ch + t/3 - 1, nw = cw + t%3 - 1;
        const float4 q4 = reinterpret_cast<const float4*>(g_q + ((size_t)b*NPIX_OUT + nh*WO + nw)*DIM)[lane];
        float d = kv.x*q4.x + kv.y*q4.y + kv.z*q4.z + kv.w*q4.w;
        d = wredsum(d);
        const float val = (d + rpb[g*9 + t]) * scale;
        p[t] = val;
        m = fmaxf(m, val);
    }
    float s = 0.f;
#pragma unroll
    for (int t = 0; t < 9; t++){ p[t] = expf(p[t] - m); s += p[t]; }
    const float inv = 1.f/s;
#pragma unroll
    for (int t = 0; t < 9; t++) p[t] = p[t]*inv + 1e-6f;

    if (lane == 0){
        float* ao = attn_out + (size_t)id*9;
#pragma unroll
        for (int t = 0; t < 9; t++) ao[t] = p[t];
#pragma unroll
        for (int t = 0; t < 9; t++){
            const int nh = ch + t/3 - 1, nw = cw + t%3 - 1;
            atomicAdd(&g_colsum[b*NPIX_OUT + nh*WO + nw], p[t]);
        }
    }
}

// ---------------- aggregation: A_col + upd + residual + xout split -----------
__global__ void upd_kernel(const float* __restrict__ attn_in,
                           float* __restrict__ acol_out)
{
    const int tid = threadIdx.x, warp = tid >> 5, lane = tid & 31;
    const int id = blockIdx.x*4 + warp;
    const int b  = id >> 12;
    const int hw = id & 4095;
    const int h = hw >> 6, w = hw & 63;
    const int ch = min(max(h,1), HO-2), cw = min(max(w,1), WO-2);

    float inv_dn[9];
#pragma unroll
    for (int t = 0; t < 9; t++){
        const int nh = ch + t/3 - 1, nw = cw + t%3 - 1;
        inv_dn[t] = 1.0f / (g_colsum[b*NPIX_OUT + nh*WO + nw] + 1e-8f);
    }
    float4 acc = make_float4(0.f,0.f,0.f,0.f);
#pragma unroll
    for (int g = 0; g < 4; g++){
        const int ga = g >> 1, gb = g & 1;
        const size_t base = ((size_t)((b*4 + g)*NPIX_OUT) + hw)*9;
        const float* ab = attn_in + base;
        float* cb = acol_out + base;
#pragma unroll
        for (int t = 0; t < 9; t++){
            const float coeff = ab[t] * inv_dn[t];
            if (lane == 0) cb[t] = coeff;
            const int nh = ch + t/3 - 1, nw = cw + t%3 - 1;
            const int pix = (2*nh + ga)*WI + 2*nw + gb;
            const float4 vv = reinterpret_cast<const float4*>(g_v + ((size_t)b*NPIX_IN + pix)*DIM)[lane];
            acc.x += coeff*vv.x; acc.y += coeff*vv.y; acc.z += coeff*vv.z; acc.w += coeff*vv.w;
        }
    }
    float4* xo = reinterpret_cast<float4*>(g_xout + (size_t)id*DIM);
    float4 v = xo[lane];
    v.x += acc.x; v.y += acc.y; v.z += acc.z; v.w += acc.w;
    xo[lane] = v;
    float t4[4] = {v.x, v.y, v.z, v.w};
    split_store4(g_xo_h + (size_t)id*DIM + lane*4,
                 g_xo_l + (size_t)id*DIM + lane*4, t4);
}

// ---------------- launch ------------------------------------------------------
extern "C" void kernel_launch(void* const* d_in, const int* in_sizes, int n_in,
                              void* d_out, int out_size)
{
    const float* x      = (const float*)d_in[0];
    const float* convw  = (const float*)d_in[1];
    const float* q_w    = (const float*)d_in[2];
    const float* k_w    = (const float*)d_in[3];
    const float* v_w    = (const float*)d_in[4];
    const float* w1     = (const float*)d_in[5];
    const float* b1     = (const float*)d_in[6];
    const float* w2     = (const float*)d_in[7];
    const float* b2     = (const float*)d_in[8];
    const float* lin_g  = (const float*)d_in[9];
    const float* lin_b  = (const float*)d_in[10];
    const float* lout_g = (const float*)d_in[11];
    const float* lout_b = (const float*)d_in[12];
    const float* tau    = (const float*)d_in[13];
    const float* rpb    = (const float*)d_in[14];

    float* out      = (float*)d_out;
    float* out_x    = out;
    float* out_attn = out + (size_t)NROWS_OUT*DIM;
    float* out_acol = out_attn + (size_t)BATCH*4*NPIX_OUT*9;

    float *pk, *pv, *pq, *pxout;
    cudaGetSymbolAddress((void**)&pk,    g_k);
    cudaGetSymbolAddress((void**)&pv,    g_v);
    cudaGetSymbolAddress((void**)&pq,    g_q);
    cudaGetSymbolAddress((void**)&pxout, g_xout);
    __nv_bfloat16 *pxh,*pxl,*plih,*plil,*poh,*pol,*pqh,*pql,*phh,*phl;
    __nv_bfloat16 *wqh,*wql,*wkh,*wkl,*wvh,*wvl,*w1h,*w1l,*w2h,*w2l;
    cudaGetSymbolAddress((void**)&pxh,  g_x_h);   cudaGetSymbolAddress((void**)&pxl,  g_x_l);
    cudaGetSymbolAddress((void**)&plih, g_xli_h); cudaGetSymbolAddress((void**)&plil, g_xli_l);
    cudaGetSymbolAddress((void**)&poh,  g_xo_h);  cudaGetSymbolAddress((void**)&pol,  g_xo_l);
    cudaGetSymbolAddress((void**)&pqh,  g_xq_h);  cudaGetSymbolAddress((void**)&pql,  g_xq_l);
    cudaGetSymbolAddress((void**)&phh,  g_hh_h);  cudaGetSymbolAddress((void**)&phl,  g_hh_l);
    cudaGetSymbolAddress((void**)&wqh,  g_wq_h);  cudaGetSymbolAddress((void**)&wql,  g_wq_l);
    cudaGetSymbolAddress((void**)&wkh,  g_wk_h);  cudaGetSymbolAddress((void**)&wkl,  g_wk_l);
    cudaGetSymbolAddress((void**)&wvh,  g_wv_h);  cudaGetSymbolAddress((void**)&wvl,  g_wv_l);
    cudaGetSymbolAddress((void**)&w1h,  g_w1_h);  cudaGetSymbolAddress((void**)&w1l,  g_w1_l);
    cudaGetSymbolAddress((void**)&w2h,  g_w2_h);  cudaGetSymbolAddress((void**)&w2l,  g_w2_l);

    cudaFuncSetAttribute(gemm_mma, cudaFuncAttributeMaxDynamicSharedMemorySize, SMEM_MMA);
    cudaFuncSetAttribute(conv_mma, cudaFuncAttributeMaxDynamicSharedMemorySize, SMEM_MMA);

    // ---- preprocessing ----
    conv_split_kernel<<<(9*DIM*DIM + 255)/256, 256>>>(convw);
    tsplit_kernel<<<(DIM*DIM)/256, 256>>>(q_w, wqh, wql, DIM, DIM);
    tsplit_kernel<<<(DIM*DIM)/256, 256>>>(k_w, wkh, wkl, DIM, DIM);
    tsplit_kernel<<<(DIM*DIM)/256, 256>>>(v_w, wvh, wvl, DIM, DIM);
    tsplit_kernel<<<(2*DIM*DIM)/256, 256>>>(w1, w1h, w1l, DIM, 2*DIM);   // -> [256,128]
    tsplit_kernel<<<(2*DIM*DIM)/256, 256>>>(w2, w2h, w2l, 2*DIM, DIM);   // -> [128,256]
    split_kernel<false><<<NROWS_IN/8, 256>>>(x, pxh, pxl, nullptr, nullptr);
    split_kernel<true ><<<NROWS_IN/8, 256>>>(x, plih, plil, lin_g, lin_b);

    // k = LN_in(x) @ k_w ; v = x @ v_w
    gemm_mma<<<NROWS_IN/128, 256, SMEM_MMA>>>(plih, plil, 128, wkh, wkl,
        nullptr, nullptr, nullptr, pk, 128, nullptr, nullptr, nullptr, nullptr, 0,
        EPI_STORE, 0);
    gemm_mma<<<NROWS_IN/128, 256, SMEM_MMA>>>(pxh, pxl, 128, wvh, wvl,
        nullptr, nullptr, nullptr, pv, 128, nullptr, nullptr, nullptr, nullptr, 0,
        EPI_STORE, 0);
    conv_mma<<<NROWS_OUT/128, 256, SMEM_MMA>>>(lout_g, lout_b);

    for (int it = 0; it < 3; it++){
        zero_colsum_kernel<<<(BATCH*NPIX_OUT)/256, 256>>>();
        // q = LN(x_out) @ q_w
        gemm_mma<<<NROWS_OUT/128, 256, SMEM_MMA>>>(pqh, pql, 128, wqh, wql,
            nullptr, nullptr, nullptr, pq, 128, nullptr, nullptr, nullptr, nullptr, 0,
            EPI_STORE, 0);
        attn_kernel<<<(BATCH*4*NPIX_OUT)/4, 128>>>(rpb, tau, out_attn);
        upd_kernel<<<NROWS_OUT/4, 128>>>(out_attn, out_acol);
        // h = gelu(x_out @ w1 + b1) -> bf16 split
        gemm_mma<<<dim3(NROWS_OUT/128, 2), 256, SMEM_MMA>>>(poh, pol, 128, w1h, w1l,
            b1, nullptr, nullptr, nullptr, 0, nullptr, nullptr, phh, phl, 256,
            EPI_GELU, 0);
        // x_out += LN(h @ w2 + b2); xq = LN(x_out) split
        gemm_mma<<<NROWS_OUT/128, 256, SMEM_MMA>>>(phh, phl, 256, w2h, w2l,
            b2, lout_g, lout_b, nullptr, 0, pxout, out_x, pqh, pql, 128,
            EPI_LNRES, it == 2 ? 1 : 0);
    }
    (void)in_sizes; (void)n_in; (void)out_size;
}